// round 8
// baseline (speedup 1.0000x reference)
#include <cuda_runtime.h>
#include <cuda_fp16.h>

#define MAXN 100000
#define MAXE 1600000
#define SCAN_BLK 1024

// ---------------- scratch (device globals; no allocations allowed) ----------
__device__ __align__(16) __half2  g_h1h[MAXN * 64];   // h1 fp16, 128 ch/row
__device__ __align__(16) float    g_as1[MAXN * 4];
__device__ __align__(16) float    g_ad1[MAXN * 4];
__device__ float                  g_h2[MAXN];
__device__ int                    g_is64;
__device__ int g_deg[MAXN];
__device__ int g_rowptr[MAXN + 1];
__device__ int g_rank[MAXE];
__device__ int g_esrc[MAXE];
__device__ unsigned long long g_scanpack[128];        // (flag<<32)|value
// W1 as fp16 hi/lo, stored [n][k] row-major (k contiguous) for mma B operand
__device__ __align__(16) __half g_W1h_hi[128 * 128];
__device__ __align__(16) __half g_W1h_lo[128 * 128];

__device__ __forceinline__ float lrelu(float v) { return v > 0.f ? v : 0.2f * v; }

__device__ __forceinline__ void edge_fetch(const void* ei, int e_cnt, int i,
                                           int is64, int& src, int& dst) {
    if (is64) {
        const long long* p = (const long long*)ei;
        src = (int)p[i];
        dst = (int)p[e_cnt + i];
    } else {
        const int* p = (const int*)ei;
        src = p[i];
        dst = p[e_cnt + i];
    }
}

__device__ __forceinline__ unsigned smem_u32(const void* p) {
    unsigned a;
    asm("{ .reg .u64 t; cvta.to.shared.u64 t, %1; cvt.u32.u64 %0, t; }"
        : "=r"(a) : "l"(p));
    return a;
}

__device__ __forceinline__ void ldsm_x4(unsigned* r, unsigned addr) {
    asm volatile("ldmatrix.sync.aligned.m8n8.x4.shared.b16 {%0,%1,%2,%3}, [%4];"
                 : "=r"(r[0]), "=r"(r[1]), "=r"(r[2]), "=r"(r[3]) : "r"(addr));
}
__device__ __forceinline__ void ldsm_x2(unsigned* r, unsigned addr) {
    asm volatile("ldmatrix.sync.aligned.m8n8.x2.shared.b16 {%0,%1}, [%2];"
                 : "=r"(r[0]), "=r"(r[1]) : "r"(addr));
}
__device__ __forceinline__ void mma16816(float* d, const unsigned* a,
                                         const unsigned* b) {
    asm volatile(
        "mma.sync.aligned.m16n8k16.row.col.f32.f16.f16.f32 "
        "{%0,%1,%2,%3}, {%4,%5,%6,%7}, {%8,%9}, {%0,%1,%2,%3};"
        : "+f"(d[0]), "+f"(d[1]), "+f"(d[2]), "+f"(d[3])
        : "r"(a[0]), "r"(a[1]), "r"(a[2]), "r"(a[3]), "r"(b[0]), "r"(b[1]));
}

// ---------------- init: zero deg + scan flags, detect dtype, convert W ------
__global__ void detect_init_kernel(const unsigned* __restrict__ ei_u32,
                                   int e_cnt, int n,
                                   const float* __restrict__ W) {
    int gid = blockIdx.x * blockDim.x + threadIdx.x;
    int stride = gridDim.x * blockDim.x;
    for (int i = gid; i < n; i += stride) g_deg[i] = 0;
    if (gid < 128) g_scanpack[gid] = 0ull;
    for (int i = gid; i < 128 * 128; i += stride) {
        int k = i >> 7, nn = i & 127;          // W[k][nn] -> B[nn][k]
        float w = W[i];
        __half hi = __float2half_rn(w);
        __half lo = __float2half_rn(w - __half2float(hi));
        g_W1h_hi[nn * 128 + k] = hi;
        g_W1h_lo[nn * 128 + k] = lo;
    }
    if (blockIdx.x == 0) {
        __shared__ int bad;
        if (threadIdx.x == 0) bad = 0;
        __syncthreads();
        int samples = e_cnt < 4096 ? e_cnt : 4096;
        for (int i = threadIdx.x; i < samples; i += blockDim.x)
            if (ei_u32[2 * i + 1] != 0u) bad = 1;
        __syncthreads();
        if (threadIdx.x == 0) g_is64 = bad ? 0 : 1;
    }
}

// ---------------- CSR: single-pass scan (warp shuffles + lookback) ----------
__global__ void scan_kernel(int n, int tot) {
    __shared__ int warpsum[32];
    __shared__ int s_prev;
    int t = threadIdx.x, b = blockIdx.x;
    int i = b * SCAN_BLK + t;
    int lane = t & 31, wid = t >> 5;
    int val = (i < n) ? g_deg[i] : 0;
    int x = val;
#pragma unroll
    for (int o = 1; o < 32; o <<= 1) {
        int y = __shfl_up_sync(0xffffffffu, x, o);
        if (lane >= o) x += y;
    }
    if (lane == 31) warpsum[wid] = x;
    __syncthreads();
    if (wid == 0) {
        int wv = warpsum[lane];
#pragma unroll
        for (int o = 1; o < 32; o <<= 1) {
            int y = __shfl_up_sync(0xffffffffu, wv, o);
            if (lane >= o) wv += y;
        }
        warpsum[lane] = wv;
    }
    __syncthreads();
    int incl = x + (wid ? warpsum[wid - 1] : 0);
    int agg = warpsum[31];

    if (b == 0) {
        if (t == 0) {
            *(volatile unsigned long long*)&g_scanpack[0] =
                (2ull << 32) | (unsigned)agg;
            s_prev = 0;
        }
    } else if (t < 32) {
        if (t == 0)
            *(volatile unsigned long long*)&g_scanpack[b] =
                (1ull << 32) | (unsigned)agg;
        __syncwarp();
        int sum = 0;
        int base = b - 1;
        for (;;) {
            int j = base - lane;
            unsigned long long w;
            unsigned f;
            for (;;) {
                w = (j >= 0) ? *(volatile unsigned long long*)&g_scanpack[j]
                             : (2ull << 32);
                f = (unsigned)(w >> 32);
                if (__all_sync(0xffffffffu, f != 0u)) break;
            }
            unsigned m2 = __ballot_sync(0xffffffffu, f == 2u);
            int fl = m2 ? (__ffs(m2) - 1) : 32;
            int take = (lane <= fl) ? (int)(unsigned)w : 0;
#pragma unroll
            for (int o = 16; o > 0; o >>= 1)
                take += __shfl_xor_sync(0xffffffffu, take, o);
            sum += take;
            if (m2) break;
            base -= 32;
        }
        if (t == 0) {
            *(volatile unsigned long long*)&g_scanpack[b] =
                (2ull << 32) | (unsigned)(sum + agg);
            s_prev = sum;
        }
    }
    __syncthreads();
    int pre = s_prev;
    if (i < n) g_rowptr[i] = pre + incl - val;
    if (i == 0) g_rowptr[n] = tot;
}

// ---------------- CSR: scatter (rank-based, no atomics, 4-edge ILP) ---------
__global__ void scatter_kernel(const void* __restrict__ ei, int e_cnt) {
    int base = blockIdx.x * 1024 + threadIdx.x;
    int is64 = g_is64;
#pragma unroll
    for (int j = 0; j < 4; j++) {
        int i = base + j * 256;
        if (i < e_cnt) {
            int src, dst;
            edge_fetch(ei, e_cnt, i, is64, src, dst);
            g_esrc[g_rowptr[dst] + g_rank[i]] = src;
        }
    }
}

// ---------------- GEMM1 (HMMA split-fp16) + fused hist/rank + att epilogue --
#define TS 136
#define TILE_B (128 * TS * 2)          // 34816 bytes
#define OFF_AH 0
#define OFF_AL TILE_B
#define OFF_BH (2 * TILE_B)
#define OFF_BL (3 * TILE_B)
#define GEMM_SMEM (4 * TILE_B)         // 139264

__global__ void __launch_bounds__(256, 1)
gemm1_kernel(const float* __restrict__ x,
             const float* __restrict__ att_s,
             const float* __restrict__ att_d, int n,
             const void* __restrict__ ei, int e_cnt) {
    extern __shared__ char smc[];
    unsigned sbase = smem_u32(smc);
    int t = threadIdx.x, lane = t & 31, w = t >> 5;

    // B tiles: copy [n][k] fp16 images into padded smem rows
    {
        const uint4* bh = (const uint4*)g_W1h_hi;
        const uint4* bl = (const uint4*)g_W1h_lo;
#pragma unroll
        for (int i = 0; i < 8; i++) {
            int idx = t + i * 256;         // 0..2047 uint4s (16 per row)
            int row = idx >> 4, c8 = idx & 15;
            *(uint4*)(smc + OFF_BH + row * 272 + c8 * 16) = bh[idx];
            *(uint4*)(smc + OFF_BL + row * 272 + c8 * 16) = bl[idx];
        }
    }

    // A tile: load x fp32, split hi/lo fp16 into padded smem rows
    {
        int m = t >> 1, half = t & 1;
        int row = blockIdx.x * 128 + m;
        const float4* xr = (const float4*)(x + (size_t)row * 128 + half * 64);
#pragma unroll 4
        for (int j = 0; j < 16; j++) {
            float4 v = make_float4(0.f, 0.f, 0.f, 0.f);
            if (row < n) v = xr[j];
            __half h0 = __float2half_rn(v.x), h1 = __float2half_rn(v.y);
            __half h2 = __float2half_rn(v.z), h3 = __float2half_rn(v.w);
            __half l0 = __float2half_rn(v.x - __half2float(h0));
            __half l1 = __float2half_rn(v.y - __half2float(h1));
            __half l2 = __float2half_rn(v.z - __half2float(h2));
            __half l3 = __float2half_rn(v.w - __half2float(h3));
            int k = half * 64 + 4 * j;
            unsigned off = (unsigned)(m * 272 + k * 2);
            __half2 hp0 = __halves2half2(h0, h1), hp1 = __halves2half2(h2, h3);
            __half2 lp0 = __halves2half2(l0, l1), lp1 = __halves2half2(l2, l3);
            uint2 hp, lp;
            hp.x = *(unsigned*)&hp0; hp.y = *(unsigned*)&hp1;
            lp.x = *(unsigned*)&lp0; lp.y = *(unsigned*)&lp1;
            *(uint2*)(smc + OFF_AH + off) = hp;
            *(uint2*)(smc + OFF_AL + off) = lp;
        }
    }

    // Fused CSR histogram + rank capture (overlaps with tensor work below).
    {
        int is64 = g_is64;
        int stride = gridDim.x * blockDim.x;
        if (is64) {
            const long long* p = (const long long*)ei + e_cnt;
            for (int i = blockIdx.x * blockDim.x + t; i < e_cnt; i += stride)
                g_rank[i] = atomicAdd(&g_deg[(int)p[i]], 1);
        } else {
            const int* p = (const int*)ei + e_cnt;
            for (int i = blockIdx.x * blockDim.x + t; i < e_cnt; i += stride)
                g_rank[i] = atomicAdd(&g_deg[p[i]], 1);
        }
    }
    __syncthreads();

    int m0 = w * 16;
    float acc[16][4];
#pragma unroll
    for (int nt = 0; nt < 16; nt++)
#pragma unroll
        for (int j = 0; j < 4; j++) acc[nt][j] = 0.f;

    unsigned aBase = sbase + OFF_AH +
        (unsigned)((m0 + (lane & 15)) * 272 + ((lane >> 4) * 8) * 2);
    unsigned bRow  = (unsigned)(lane & 7);
    unsigned bKoff = (unsigned)(((lane >> 3) & 1) * 8);

    for (int kt = 0; kt < 8; kt++) {
        unsigned aA = aBase + kt * 32;
        unsigned ah[4], al[4];
        ldsm_x4(ah, aA);
        ldsm_x4(al, aA + TILE_B);
#pragma unroll
        for (int nt = 0; nt < 16; nt++) {
            unsigned bAddr = sbase + OFF_BH +
                (unsigned)((nt * 8 + bRow) * 272 + (kt * 16 + bKoff) * 2);
            unsigned bh[2], bl[2];
            ldsm_x2(bh, bAddr);
            ldsm_x2(bl, bAddr + TILE_B);
            mma16816(acc[nt], ah, bh);
            mma16816(acc[nt], ah, bl);
            mma16816(acc[nt], al, bh);
        }
    }

    // Epilogue: thread holds rows r0 = m0+lane/4, r1 = r0+8,
    // cols n = nt*8 + 2*(lane%4) + {0,1}. Store fp16 h1 + head reductions.
    {
        int gr = lane >> 2, c = lane & 3;
        int r0 = blockIdx.x * 128 + m0 + gr;
        int r1 = r0 + 8;
        float sv0[4] = {0, 0, 0, 0}, dv0[4] = {0, 0, 0, 0};
        float sv1[4] = {0, 0, 0, 0}, dv1[4] = {0, 0, 0, 0};
#pragma unroll
        for (int nt = 0; nt < 16; nt++) {
            int col = nt * 8 + 2 * c;
            float w0 = att_s[col], w1 = att_s[col + 1];
            float u0 = att_d[col], u1 = att_d[col + 1];
            int hd = nt >> 2;
            sv0[hd] += acc[nt][0] * w0 + acc[nt][1] * w1;
            dv0[hd] += acc[nt][0] * u0 + acc[nt][1] * u1;
            sv1[hd] += acc[nt][2] * w0 + acc[nt][3] * w1;
            dv1[hd] += acc[nt][2] * u0 + acc[nt][3] * u1;
            if (r0 < n)
                g_h1h[(size_t)r0 * 64 + nt * 4 + c] =
                    __floats2half2_rn(acc[nt][0], acc[nt][1]);
            if (r1 < n)
                g_h1h[(size_t)r1 * 64 + nt * 4 + c] =
                    __floats2half2_rn(acc[nt][2], acc[nt][3]);
        }
#pragma unroll
        for (int hd = 0; hd < 4; hd++) {
#pragma unroll
            for (int o = 1; o < 4; o <<= 1) {
                sv0[hd] += __shfl_xor_sync(0xffffffffu, sv0[hd], o);
                dv0[hd] += __shfl_xor_sync(0xffffffffu, dv0[hd], o);
                sv1[hd] += __shfl_xor_sync(0xffffffffu, sv1[hd], o);
                dv1[hd] += __shfl_xor_sync(0xffffffffu, dv1[hd], o);
            }
        }
        if (c == 0) {
#pragma unroll
            for (int hd = 0; hd < 4; hd++) {
                if (r0 < n) {
                    g_as1[r0 * 4 + hd] = sv0[hd];
                    g_ad1[r0 * 4 + hd] = dv0[hd];
                }
                if (r1 < n) {
                    g_as1[r1 * 4 + hd] = sv1[hd];
                    g_ad1[r1 * 4 + hd] = dv1[hd];
                }
            }
        }
    }
}

// ---------------- layer-1 aggregation (warp per dst, half-warp edge pairs) --
// Lanes 0-15 process even edges, 16-31 odd edges; lane sl owns channels
// 8sl..8sl+7 (head sl>>2) via one uint4 load per edge. shfl-xor-16 merges.
__global__ void agg1_kernel(const float* __restrict__ b1,
                            const float* __restrict__ W2, int n) {
    int v = (blockIdx.x * blockDim.x + threadIdx.x) >> 5;
    int lane = threadIdx.x & 31;
    if (v >= n) return;
    int sl = lane & 15;
    int half = lane >> 4;
    int hd = sl >> 2;
    int beg = g_rowptr[v];
    int end = g_rowptr[v + 1];
    float adv = g_ad1[v * 4 + hd];
    const uint4* H4 = (const uint4*)g_h1h;   // 16 uint4 per 128-ch row

    float acc[8] = {0.f, 0.f, 0.f, 0.f, 0.f, 0.f, 0.f, 0.f};
    float den = 0.f;

    // self-loop (half 0 only; merged by the xor-16 combine)
    if (half == 0) {
        float exs = __expf(lrelu(g_as1[v * 4 + hd] + adv));
        uint4 pv = H4[(size_t)v * 16 + sl];
        float2 q0 = __half22float2(*(__half2*)&pv.x);
        float2 q1 = __half22float2(*(__half2*)&pv.y);
        float2 q2 = __half22float2(*(__half2*)&pv.z);
        float2 q3 = __half22float2(*(__half2*)&pv.w);
        den = exs;
        acc[0] = q0.x * exs; acc[1] = q0.y * exs;
        acc[2] = q1.x * exs; acc[3] = q1.y * exs;
        acc[4] = q2.x * exs; acc[5] = q2.y * exs;
        acc[6] = q3.x * exs; acc[7] = q3.y * exs;
    }

    int e = beg + half;
    for (; e + 2 < end; e += 4) {
        int s0 = g_esrc[e], s1 = g_esrc[e + 2];
        float a0 = g_as1[s0 * 4 + hd], a1 = g_as1[s1 * 4 + hd];
        uint4 p0 = H4[(size_t)s0 * 16 + sl];
        uint4 p1 = H4[(size_t)s1 * 16 + sl];
        float e0 = __expf(lrelu(a0 + adv));
        float e1 = __expf(lrelu(a1 + adv));
        den += e0 + e1;
        float2 q;
        q = __half22float2(*(__half2*)&p0.x); acc[0] += q.x * e0; acc[1] += q.y * e0;
        q = __half22float2(*(__half2*)&p0.y); acc[2] += q.x * e0; acc[3] += q.y * e0;
        q = __half22float2(*(__half2*)&p0.z); acc[4] += q.x * e0; acc[5] += q.y * e0;
        q = __half22float2(*(__half2*)&p0.w); acc[6] += q.x * e0; acc[7] += q.y * e0;
        q = __half22float2(*(__half2*)&p1.x); acc[0] += q.x * e1; acc[1] += q.y * e1;
        q = __half22float2(*(__half2*)&p1.y); acc[2] += q.x * e1; acc[3] += q.y * e1;
        q = __half22float2(*(__half2*)&p1.z); acc[4] += q.x * e1; acc[5] += q.y * e1;
        q = __half22float2(*(__half2*)&p1.w); acc[6] += q.x * e1; acc[7] += q.y * e1;
    }
    if (e < end) {
        int s0 = g_esrc[e];
        float e0 = __expf(lrelu(g_as1[s0 * 4 + hd] + adv));
        uint4 p0 = H4[(size_t)s0 * 16 + sl];
        den += e0;
        float2 q;
        q = __half22float2(*(__half2*)&p0.x); acc[0] += q.x * e0; acc[1] += q.y * e0;
        q = __half22float2(*(__half2*)&p0.y); acc[2] += q.x * e0; acc[3] += q.y * e0;
        q = __half22float2(*(__half2*)&p0.z); acc[4] += q.x * e0; acc[5] += q.y * e0;
        q = __half22float2(*(__half2*)&p0.w); acc[6] += q.x * e0; acc[7] += q.y * e0;
    }

    // merge halves (lane l <-> l+16 hold same channels, different edges)
    den += __shfl_xor_sync(0xffffffffu, den, 16);
#pragma unroll
    for (int j = 0; j < 8; j++)
        acc[j] += __shfl_xor_sync(0xffffffffu, acc[j], 16);

    float inv = 1.f / (den + 1e-16f);
    float4 bb0 = ((const float4*)b1)[sl * 2];
    float4 bb1 = ((const float4*)b1)[sl * 2 + 1];
    float4 w0  = ((const float4*)W2)[sl * 2];
    float4 w1  = ((const float4*)W2)[sl * 2 + 1];
    float s =
        fmaxf(acc[0] * inv + bb0.x, 0.f) * w0.x +
        fmaxf(acc[1] * inv + bb0.y, 0.f) * w0.y +
        fmaxf(acc[2] * inv + bb0.z, 0.f) * w0.z +
        fmaxf(acc[3] * inv + bb0.w, 0.f) * w0.w +
        fmaxf(acc[4] * inv + bb1.x, 0.f) * w1.x +
        fmaxf(acc[5] * inv + bb1.y, 0.f) * w1.y +
        fmaxf(acc[6] * inv + bb1.z, 0.f) * w1.z +
        fmaxf(acc[7] * inv + bb1.w, 0.f) * w1.w;
#pragma unroll
    for (int o = 1; o < 16; o <<= 1) s += __shfl_xor_sync(0xffffffffu, s, o);
    if (lane == 0) g_h2[v] = s;
}

// ---------------- layer-2 aggregation (CSR, thread per dst; self-loop fused) -
__global__ void agg2_kernel(const float* __restrict__ att_s2,
                            const float* __restrict__ att_d2,
                            const float* __restrict__ b2,
                            float* __restrict__ out, int n) {
    int v = blockIdx.x * blockDim.x + threadIdx.x;
    if (v >= n) return;
    float as2 = att_s2[0];
    float hv = g_h2[v];
    float adv = hv * att_d2[0];
    int beg = g_rowptr[v];
    int end = g_rowptr[v + 1];
    float exs = __expf(lrelu(hv * as2 + adv));
    float den = exs, num = hv * exs;
    int e = beg;
    for (; e + 3 < end; e += 4) {
        int s0 = g_esrc[e], s1 = g_esrc[e + 1];
        int s2 = g_esrc[e + 2], s3 = g_esrc[e + 3];
        float h0 = g_h2[s0], h1 = g_h2[s1], h2 = g_h2[s2], h3 = g_h2[s3];
        float e0 = __expf(lrelu(h0 * as2 + adv));
        float e1 = __expf(lrelu(h1 * as2 + adv));
        float e2 = __expf(lrelu(h2 * as2 + adv));
        float e3 = __expf(lrelu(h3 * as2 + adv));
        den += (e0 + e1) + (e2 + e3);
        num += (h0 * e0 + h1 * e1) + (h2 * e2 + h3 * e3);
    }
    for (; e < end; e++) {
        float h0 = g_h2[g_esrc[e]];
        float e0 = __expf(lrelu(h0 * as2 + adv));
        den += e0;
        num += h0 * e0;
    }
    out[v] = num / (den + 1e-16f) + b2[0];
}

// ---------------- launch ------------------------------------------------------
extern "C" void kernel_launch(void* const* d_in, const int* in_sizes, int n_in,
                              void* d_out, int out_size) {
    const float* x        = (const float*)d_in[0];
    const void*  ei       = d_in[1];
    const float* W1       = (const float*)d_in[2];
    const float* att_src1 = (const float*)d_in[3];
    const float* att_dst1 = (const float*)d_in[4];
    const float* b1       = (const float*)d_in[5];
    const float* W2       = (const float*)d_in[6];
    const float* att_src2 = (const float*)d_in[7];
    const float* att_dst2 = (const float*)d_in[8];
    const float* b2       = (const float*)d_in[9];
    float* out = (float*)d_out;

    int n = in_sizes[0] / 128;
    int e = in_sizes[1] / 2;
    int nb = (n + SCAN_BLK - 1) / SCAN_BLK;

    cudaFuncSetAttribute(gemm1_kernel,
                         cudaFuncAttributeMaxDynamicSharedMemorySize, GEMM_SMEM);

    detect_init_kernel<<<64, 256>>>((const unsigned*)ei, e, n, W1);
    gemm1_kernel<<<(n + 127) / 128, 256, GEMM_SMEM>>>(x, att_src1, att_dst1, n,
                                                      ei, e);
    scan_kernel<<<nb, SCAN_BLK>>>(n, e);
    scatter_kernel<<<(e + 1023) / 1024, 256>>>(ei, e);
    agg1_kernel<<<(n + 7) / 8, 256>>>(b1, W2, n);
    agg2_kernel<<<(n + 255) / 256, 256>>>(att_src2, att_dst2, b2, out, n);
}

// round 9
// speedup vs baseline: 1.0503x; 1.0503x over previous
#include <cuda_runtime.h>
#include <cuda_fp16.h>

#define MAXN 100000
#define MAXE 1600000
#define SCAN_BLK 1024

// ---------------- scratch (device globals; no allocations allowed) ----------
__device__ __align__(16) __half2  g_h1h[MAXN * 64];   // h1 fp16, 128 ch/row
__device__ __align__(16) float    g_as1[MAXN * 4];
__device__ __align__(16) float    g_ad1[MAXN * 4];
__device__ float                  g_h2[MAXN];
__device__ int                    g_is64;
__device__ int g_deg[MAXN];
__device__ int g_rowptr[MAXN + 1];
__device__ int g_rank[MAXE];
__device__ int g_esrc[MAXE];
__device__ unsigned long long g_scanpack[128];        // (flag<<32)|value
// W1 as fp16 hi/lo, stored [n][k] row-major (k contiguous) for mma B operand
__device__ __align__(16) __half g_W1h_hi[128 * 128];
__device__ __align__(16) __half g_W1h_lo[128 * 128];

__device__ __forceinline__ float lrelu(float v) { return v > 0.f ? v : 0.2f * v; }

__device__ __forceinline__ void edge_fetch(const void* ei, int e_cnt, int i,
                                           int is64, int& src, int& dst) {
    if (is64) {
        const long long* p = (const long long*)ei;
        src = (int)p[i];
        dst = (int)p[e_cnt + i];
    } else {
        const int* p = (const int*)ei;
        src = p[i];
        dst = p[e_cnt + i];
    }
}

__device__ __forceinline__ unsigned smem_u32(const void* p) {
    unsigned a;
    asm("{ .reg .u64 t; cvta.to.shared.u64 t, %1; cvt.u32.u64 %0, t; }"
        : "=r"(a) : "l"(p));
    return a;
}

__device__ __forceinline__ void ldsm_x4(unsigned* r, unsigned addr) {
    asm volatile("ldmatrix.sync.aligned.m8n8.x4.shared.b16 {%0,%1,%2,%3}, [%4];"
                 : "=r"(r[0]), "=r"(r[1]), "=r"(r[2]), "=r"(r[3]) : "r"(addr));
}
__device__ __forceinline__ void ldsm_x2(unsigned* r, unsigned addr) {
    asm volatile("ldmatrix.sync.aligned.m8n8.x2.shared.b16 {%0,%1}, [%2];"
                 : "=r"(r[0]), "=r"(r[1]) : "r"(addr));
}
__device__ __forceinline__ void mma16816(float* d, const unsigned* a,
                                         const unsigned* b) {
    asm volatile(
        "mma.sync.aligned.m16n8k16.row.col.f32.f16.f16.f32 "
        "{%0,%1,%2,%3}, {%4,%5,%6,%7}, {%8,%9}, {%0,%1,%2,%3};"
        : "+f"(d[0]), "+f"(d[1]), "+f"(d[2]), "+f"(d[3])
        : "r"(a[0]), "r"(a[1]), "r"(a[2]), "r"(a[3]), "r"(b[0]), "r"(b[1]));
}

// ---------------- init: zero deg + scan flags, detect dtype, convert W ------
__global__ void detect_init_kernel(const unsigned* __restrict__ ei_u32,
                                   int e_cnt, int n,
                                   const float* __restrict__ W) {
    int gid = blockIdx.x * blockDim.x + threadIdx.x;
    int stride = gridDim.x * blockDim.x;
    for (int i = gid; i < n; i += stride) g_deg[i] = 0;
    if (gid < 128) g_scanpack[gid] = 0ull;
    for (int i = gid; i < 128 * 128; i += stride) {
        int k = i >> 7, nn = i & 127;          // W[k][nn] -> B[nn][k]
        float w = W[i];
        __half hi = __float2half_rn(w);
        __half lo = __float2half_rn(w - __half2float(hi));
        g_W1h_hi[nn * 128 + k] = hi;
        g_W1h_lo[nn * 128 + k] = lo;
    }
    if (blockIdx.x == 0) {
        __shared__ int bad;
        if (threadIdx.x == 0) bad = 0;
        __syncthreads();
        int samples = e_cnt < 4096 ? e_cnt : 4096;
        for (int i = threadIdx.x; i < samples; i += blockDim.x)
            if (ei_u32[2 * i + 1] != 0u) bad = 1;
        __syncthreads();
        if (threadIdx.x == 0) g_is64 = bad ? 0 : 1;
    }
}

// ---------------- CSR: histogram + rank capture (4-edge ILP) ----------------
__global__ void hist_kernel(const void* __restrict__ ei, int e_cnt) {
    int base = blockIdx.x * 1024 + threadIdx.x;
    int is64 = g_is64;
    int d[4];
#pragma unroll
    for (int j = 0; j < 4; j++) {
        int i = base + j * 256;
        if (i < e_cnt) {
            d[j] = is64 ? (int)((const long long*)ei)[e_cnt + i]
                        : ((const int*)ei)[e_cnt + i];
        }
    }
#pragma unroll
    for (int j = 0; j < 4; j++) {
        int i = base + j * 256;
        if (i < e_cnt) g_rank[i] = atomicAdd(&g_deg[d[j]], 1);
    }
}

// ---------------- CSR: single-pass scan (warp shuffles + lookback) ----------
__global__ void scan_kernel(int n, int tot) {
    __shared__ int warpsum[32];
    __shared__ int s_prev;
    int t = threadIdx.x, b = blockIdx.x;
    int i = b * SCAN_BLK + t;
    int lane = t & 31, wid = t >> 5;
    int val = (i < n) ? g_deg[i] : 0;
    int x = val;
#pragma unroll
    for (int o = 1; o < 32; o <<= 1) {
        int y = __shfl_up_sync(0xffffffffu, x, o);
        if (lane >= o) x += y;
    }
    if (lane == 31) warpsum[wid] = x;
    __syncthreads();
    if (wid == 0) {
        int wv = warpsum[lane];
#pragma unroll
        for (int o = 1; o < 32; o <<= 1) {
            int y = __shfl_up_sync(0xffffffffu, wv, o);
            if (lane >= o) wv += y;
        }
        warpsum[lane] = wv;
    }
    __syncthreads();
    int incl = x + (wid ? warpsum[wid - 1] : 0);
    int agg = warpsum[31];

    if (b == 0) {
        if (t == 0) {
            *(volatile unsigned long long*)&g_scanpack[0] =
                (2ull << 32) | (unsigned)agg;
            s_prev = 0;
        }
    } else if (t < 32) {
        if (t == 0)
            *(volatile unsigned long long*)&g_scanpack[b] =
                (1ull << 32) | (unsigned)agg;
        __syncwarp();
        int sum = 0;
        int base = b - 1;
        for (;;) {
            int j = base - lane;
            unsigned long long w;
            unsigned f;
            for (;;) {
                w = (j >= 0) ? *(volatile unsigned long long*)&g_scanpack[j]
                             : (2ull << 32);
                f = (unsigned)(w >> 32);
                if (__all_sync(0xffffffffu, f != 0u)) break;
            }
            unsigned m2 = __ballot_sync(0xffffffffu, f == 2u);
            int fl = m2 ? (__ffs(m2) - 1) : 32;
            int take = (lane <= fl) ? (int)(unsigned)w : 0;
#pragma unroll
            for (int o = 16; o > 0; o >>= 1)
                take += __shfl_xor_sync(0xffffffffu, take, o);
            sum += take;
            if (m2) break;
            base -= 32;
        }
        if (t == 0) {
            *(volatile unsigned long long*)&g_scanpack[b] =
                (2ull << 32) | (unsigned)(sum + agg);
            s_prev = sum;
        }
    }
    __syncthreads();
    int pre = s_prev;
    if (i < n) g_rowptr[i] = pre + incl - val;
    if (i == 0) g_rowptr[n] = tot;
}

// ---------------- CSR: scatter (rank-based, no atomics, 4-edge ILP) ---------
__global__ void scatter_kernel(const void* __restrict__ ei, int e_cnt) {
    int base = blockIdx.x * 1024 + threadIdx.x;
    int is64 = g_is64;
#pragma unroll
    for (int j = 0; j < 4; j++) {
        int i = base + j * 256;
        if (i < e_cnt) {
            int src, dst;
            edge_fetch(ei, e_cnt, i, is64, src, dst);
            g_esrc[g_rowptr[dst] + g_rank[i]] = src;
        }
    }
}

// ---------------- GEMM1 (HMMA split-fp16) + fused attention epilogue --------
#define TS 136
#define TILE_B (128 * TS * 2)          // 34816 bytes
#define OFF_AH 0
#define OFF_AL TILE_B
#define OFF_BH (2 * TILE_B)
#define OFF_BL (3 * TILE_B)
#define GEMM_SMEM (4 * TILE_B)         // 139264

__global__ void __launch_bounds__(256, 1)
gemm1_kernel(const float* __restrict__ x,
             const float* __restrict__ att_s,
             const float* __restrict__ att_d, int n) {
    extern __shared__ char smc[];
    unsigned sbase = smem_u32(smc);
    int t = threadIdx.x, lane = t & 31, w = t >> 5;

    // B tiles: copy [n][k] fp16 images into padded smem rows
    {
        const uint4* bh = (const uint4*)g_W1h_hi;
        const uint4* bl = (const uint4*)g_W1h_lo;
#pragma unroll
        for (int i = 0; i < 8; i++) {
            int idx = t + i * 256;         // 0..2047 uint4s (16 per row)
            int row = idx >> 4, c8 = idx & 15;
            *(uint4*)(smc + OFF_BH + row * 272 + c8 * 16) = bh[idx];
            *(uint4*)(smc + OFF_BL + row * 272 + c8 * 16) = bl[idx];
        }
    }

    // A tile: load x fp32, split hi/lo fp16 into padded smem rows
    {
        int m = t >> 1, half = t & 1;
        int row = blockIdx.x * 128 + m;
        const float4* xr = (const float4*)(x + (size_t)row * 128 + half * 64);
#pragma unroll 4
        for (int j = 0; j < 16; j++) {
            float4 v = make_float4(0.f, 0.f, 0.f, 0.f);
            if (row < n) v = xr[j];
            __half h0 = __float2half_rn(v.x), h1 = __float2half_rn(v.y);
            __half h2 = __float2half_rn(v.z), h3 = __float2half_rn(v.w);
            __half l0 = __float2half_rn(v.x - __half2float(h0));
            __half l1 = __float2half_rn(v.y - __half2float(h1));
            __half l2 = __float2half_rn(v.z - __half2float(h2));
            __half l3 = __float2half_rn(v.w - __half2float(h3));
            int k = half * 64 + 4 * j;
            unsigned off = (unsigned)(m * 272 + k * 2);
            __half2 hp0 = __halves2half2(h0, h1), hp1 = __halves2half2(h2, h3);
            __half2 lp0 = __halves2half2(l0, l1), lp1 = __halves2half2(l2, l3);
            uint2 hp, lp;
            hp.x = *(unsigned*)&hp0; hp.y = *(unsigned*)&hp1;
            lp.x = *(unsigned*)&lp0; lp.y = *(unsigned*)&lp1;
            *(uint2*)(smc + OFF_AH + off) = hp;
            *(uint2*)(smc + OFF_AL + off) = lp;
        }
    }
    __syncthreads();

    int m0 = w * 16;
    float acc[16][4];
#pragma unroll
    for (int nt = 0; nt < 16; nt++)
#pragma unroll
        for (int j = 0; j < 4; j++) acc[nt][j] = 0.f;

    unsigned aBase = sbase + OFF_AH +
        (unsigned)((m0 + (lane & 15)) * 272 + ((lane >> 4) * 8) * 2);
    unsigned bRow  = (unsigned)(lane & 7);
    unsigned bKoff = (unsigned)(((lane >> 3) & 1) * 8);

    for (int kt = 0; kt < 8; kt++) {
        unsigned aA = aBase + kt * 32;
        unsigned ah[4], al[4];
        ldsm_x4(ah, aA);
        ldsm_x4(al, aA + TILE_B);
#pragma unroll
        for (int nt = 0; nt < 16; nt++) {
            unsigned bAddr = sbase + OFF_BH +
                (unsigned)((nt * 8 + bRow) * 272 + (kt * 16 + bKoff) * 2);
            unsigned bh[2], bl[2];
            ldsm_x2(bh, bAddr);
            ldsm_x2(bl, bAddr + TILE_B);
            mma16816(acc[nt], ah, bh);
            mma16816(acc[nt], ah, bl);
            mma16816(acc[nt], al, bh);
        }
    }

    // Epilogue: thread holds rows r0 = m0+lane/4, r1 = r0+8,
    // cols n = nt*8 + 2*(lane%4) + {0,1}. Store fp16 h1 + head reductions.
    {
        int gr = lane >> 2, c = lane & 3;
        int r0 = blockIdx.x * 128 + m0 + gr;
        int r1 = r0 + 8;
        float sv0[4] = {0, 0, 0, 0}, dv0[4] = {0, 0, 0, 0};
        float sv1[4] = {0, 0, 0, 0}, dv1[4] = {0, 0, 0, 0};
#pragma unroll
        for (int nt = 0; nt < 16; nt++) {
            int col = nt * 8 + 2 * c;
            float w0 = att_s[col], w1 = att_s[col + 1];
            float u0 = att_d[col], u1 = att_d[col + 1];
            int hd = nt >> 2;
            sv0[hd] += acc[nt][0] * w0 + acc[nt][1] * w1;
            dv0[hd] += acc[nt][0] * u0 + acc[nt][1] * u1;
            sv1[hd] += acc[nt][2] * w0 + acc[nt][3] * w1;
            dv1[hd] += acc[nt][2] * u0 + acc[nt][3] * u1;
            if (r0 < n)
                g_h1h[(size_t)r0 * 64 + nt * 4 + c] =
                    __floats2half2_rn(acc[nt][0], acc[nt][1]);
            if (r1 < n)
                g_h1h[(size_t)r1 * 64 + nt * 4 + c] =
                    __floats2half2_rn(acc[nt][2], acc[nt][3]);
        }
#pragma unroll
        for (int hd = 0; hd < 4; hd++) {
#pragma unroll
            for (int o = 1; o < 4; o <<= 1) {
                sv0[hd] += __shfl_xor_sync(0xffffffffu, sv0[hd], o);
                dv0[hd] += __shfl_xor_sync(0xffffffffu, dv0[hd], o);
                sv1[hd] += __shfl_xor_sync(0xffffffffu, sv1[hd], o);
                dv1[hd] += __shfl_xor_sync(0xffffffffu, dv1[hd], o);
            }
        }
        if (c == 0) {
#pragma unroll
            for (int hd = 0; hd < 4; hd++) {
                if (r0 < n) {
                    g_as1[r0 * 4 + hd] = sv0[hd];
                    g_ad1[r0 * 4 + hd] = dv0[hd];
                }
                if (r1 < n) {
                    g_as1[r1 * 4 + hd] = sv1[hd];
                    g_ad1[r1 * 4 + hd] = dv1[hd];
                }
            }
        }
    }
}

// ---------------- layer-1 aggregation (CSR, warp per dst; self-loop fused) --
__global__ void agg1_kernel(const float* __restrict__ b1,
                            const float* __restrict__ W2, int n) {
    int v = (blockIdx.x * blockDim.x + threadIdx.x) >> 5;
    int lane = threadIdx.x & 31;
    if (v >= n) return;
    int hd = lane >> 3;
    int beg = g_rowptr[v];
    int end = g_rowptr[v + 1];
    float adv = g_ad1[v * 4 + hd];
    const uint2* H2 = (const uint2*)g_h1h;

    // self-loop contribution (exact: loops were excluded from the CSR)
    float4 acc;
    float den;
    {
        float exs = __expf(lrelu(g_as1[v * 4 + hd] + adv));
        uint2 pv = H2[v * 32 + lane];
        float2 q0 = __half22float2(*(__half2*)&pv.x);
        float2 q1 = __half22float2(*(__half2*)&pv.y);
        den = exs;
        acc = make_float4(q0.x * exs, q0.y * exs, q1.x * exs, q1.y * exs);
    }

    int e = beg;
    for (; e + 3 < end; e += 4) {
        int s0 = g_esrc[e], s1 = g_esrc[e + 1];
        int s2 = g_esrc[e + 2], s3 = g_esrc[e + 3];
        float a0 = g_as1[s0 * 4 + hd], a1 = g_as1[s1 * 4 + hd];
        float a2 = g_as1[s2 * 4 + hd], a3 = g_as1[s3 * 4 + hd];
        uint2 p0 = H2[s0 * 32 + lane], p1 = H2[s1 * 32 + lane];
        uint2 p2 = H2[s2 * 32 + lane], p3 = H2[s3 * 32 + lane];
        float e0 = __expf(lrelu(a0 + adv)), e1 = __expf(lrelu(a1 + adv));
        float e2 = __expf(lrelu(a2 + adv)), e3 = __expf(lrelu(a3 + adv));
        den += (e0 + e1) + (e2 + e3);
        float2 q;
        q = __half22float2(*(__half2*)&p0.x); acc.x += q.x * e0; acc.y += q.y * e0;
        q = __half22float2(*(__half2*)&p0.y); acc.z += q.x * e0; acc.w += q.y * e0;
        q = __half22float2(*(__half2*)&p1.x); acc.x += q.x * e1; acc.y += q.y * e1;
        q = __half22float2(*(__half2*)&p1.y); acc.z += q.x * e1; acc.w += q.y * e1;
        q = __half22float2(*(__half2*)&p2.x); acc.x += q.x * e2; acc.y += q.y * e2;
        q = __half22float2(*(__half2*)&p2.y); acc.z += q.x * e2; acc.w += q.y * e2;
        q = __half22float2(*(__half2*)&p3.x); acc.x += q.x * e3; acc.y += q.y * e3;
        q = __half22float2(*(__half2*)&p3.y); acc.z += q.x * e3; acc.w += q.y * e3;
    }
    for (; e < end; e++) {
        int s0 = g_esrc[e];
        float e0 = __expf(lrelu(g_as1[s0 * 4 + hd] + adv));
        uint2 p0 = H2[s0 * 32 + lane];
        float2 q;
        den += e0;
        q = __half22float2(*(__half2*)&p0.x); acc.x += q.x * e0; acc.y += q.y * e0;
        q = __half22float2(*(__half2*)&p0.y); acc.z += q.x * e0; acc.w += q.y * e0;
    }

    float inv = 1.f / (den + 1e-16f);
    float4 bb = ((const float4*)b1)[lane];
    float4 w  = ((const float4*)W2)[lane];
    float x0 = fmaxf(acc.x * inv + bb.x, 0.f);
    float x1 = fmaxf(acc.y * inv + bb.y, 0.f);
    float x2 = fmaxf(acc.z * inv + bb.z, 0.f);
    float x3 = fmaxf(acc.w * inv + bb.w, 0.f);
    float s = x0 * w.x + x1 * w.y + x2 * w.z + x3 * w.w;
#pragma unroll
    for (int o = 16; o > 0; o >>= 1) s += __shfl_xor_sync(0xffffffffu, s, o);
    if (lane == 0) g_h2[v] = s;
}

// ---------------- layer-2 aggregation (CSR, thread per dst; self-loop fused) -
__global__ void agg2_kernel(const float* __restrict__ att_s2,
                            const float* __restrict__ att_d2,
                            const float* __restrict__ b2,
                            float* __restrict__ out, int n) {
    int v = blockIdx.x * blockDim.x + threadIdx.x;
    if (v >= n) return;
    float as2 = att_s2[0];
    float hv = g_h2[v];
    float adv = hv * att_d2[0];
    int beg = g_rowptr[v];
    int end = g_rowptr[v + 1];
    float exs = __expf(lrelu(hv * as2 + adv));
    float den = exs, num = hv * exs;
    int e = beg;
    for (; e + 3 < end; e += 4) {
        int s0 = g_esrc[e], s1 = g_esrc[e + 1];
        int s2 = g_esrc[e + 2], s3 = g_esrc[e + 3];
        float h0 = g_h2[s0], h1 = g_h2[s1], h2 = g_h2[s2], h3 = g_h2[s3];
        float e0 = __expf(lrelu(h0 * as2 + adv));
        float e1 = __expf(lrelu(h1 * as2 + adv));
        float e2 = __expf(lrelu(h2 * as2 + adv));
        float e3 = __expf(lrelu(h3 * as2 + adv));
        den += (e0 + e1) + (e2 + e3);
        num += (h0 * e0 + h1 * e1) + (h2 * e2 + h3 * e3);
    }
    for (; e < end; e++) {
        float h0 = g_h2[g_esrc[e]];
        float e0 = __expf(lrelu(h0 * as2 + adv));
        den += e0;
        num += h0 * e0;
    }
    out[v] = num / (den + 1e-16f) + b2[0];
}

// ---------------- launch ------------------------------------------------------
extern "C" void kernel_launch(void* const* d_in, const int* in_sizes, int n_in,
                              void* d_out, int out_size) {
    const float* x        = (const float*)d_in[0];
    const void*  ei       = d_in[1];
    const float* W1       = (const float*)d_in[2];
    const float* att_src1 = (const float*)d_in[3];
    const float* att_dst1 = (const float*)d_in[4];
    const float* b1       = (const float*)d_in[5];
    const float* W2       = (const float*)d_in[6];
    const float* att_src2 = (const float*)d_in[7];
    const float* att_dst2 = (const float*)d_in[8];
    const float* b2       = (const float*)d_in[9];
    float* out = (float*)d_out;

    int n = in_sizes[0] / 128;
    int e = in_sizes[1] / 2;
    int nb = (n + SCAN_BLK - 1) / SCAN_BLK;

    cudaFuncSetAttribute(gemm1_kernel,
                         cudaFuncAttributeMaxDynamicSharedMemorySize, GEMM_SMEM);

    detect_init_kernel<<<64, 256>>>((const unsigned*)ei, e, n, W1);
    hist_kernel<<<(e + 1023) / 1024, 256>>>(ei, e);
    gemm1_kernel<<<(n + 127) / 128, 256, GEMM_SMEM>>>(x, att_src1, att_dst1, n);
    scan_kernel<<<nb, SCAN_BLK>>>(n, e);
    scatter_kernel<<<(e + 1023) / 1024, 256>>>(ei, e);
    agg1_kernel<<<(n + 7) / 8, 256>>>(b1, W2, n);
    agg2_kernel<<<(n + 255) / 256, 256>>>(att_src2, att_dst2, b2, out, n);
}

// round 10
// speedup vs baseline: 1.1686x; 1.1126x over previous
#include <cuda_runtime.h>
#include <cuda_fp16.h>

#define MAXN 100000
#define MAXE 1600000

// ---------------- scratch (device globals; no allocations allowed) ----------
__device__ __align__(16) __half2  g_h1h[MAXN * 64];   // h1 fp16, 128 ch/row
__device__ __align__(16) float    g_as1[MAXN * 4];
__device__ __align__(16) float    g_ad1[MAXN * 4];
__device__ float                  g_h2[MAXN];
__device__ __align__(16) int g_deg[MAXN];
__device__ __align__(16) int g_rowptr[MAXN + 4];
__device__ int g_rank[MAXE];
__device__ int g_esrc[MAXE];
__device__ unsigned long long g_scanpack[128];        // (flag<<32)|value
// W1 as fp16 hi/lo, stored [n][k] row-major (k contiguous) for mma B operand
__device__ __align__(16) __half g_W1h_hi[128 * 128];
__device__ __align__(16) __half g_W1h_lo[128 * 128];

__device__ __forceinline__ float lrelu(float v) { return v > 0.f ? v : 0.2f * v; }

__device__ __forceinline__ void edge_fetch(const void* ei, int e_cnt, int i,
                                           int is64, int& src, int& dst) {
    if (is64) {
        const long long* p = (const long long*)ei;
        src = (int)p[i];
        dst = (int)p[e_cnt + i];
    } else {
        const int* p = (const int*)ei;
        src = p[i];
        dst = p[e_cnt + i];
    }
}

// per-block dtype detection: int64 iff first 32 high-words are all zero
__device__ __forceinline__ int block_detect_is64(const void* ei) {
    __shared__ int s_is64;
    if (threadIdx.x < 32) {
        unsigned hw = ((const unsigned*)ei)[2 * threadIdx.x + 1];
        unsigned nz = __ballot_sync(0xffffffffu, hw != 0u);
        if (threadIdx.x == 0) s_is64 = (nz == 0u) ? 1 : 0;
    }
    __syncthreads();
    return s_is64;
}

__device__ __forceinline__ unsigned smem_u32(const void* p) {
    unsigned a;
    asm("{ .reg .u64 t; cvta.to.shared.u64 t, %1; cvt.u32.u64 %0, t; }"
        : "=r"(a) : "l"(p));
    return a;
}

__device__ __forceinline__ void ldsm_x2(unsigned* r, unsigned addr) {
    asm volatile("ldmatrix.sync.aligned.m8n8.x2.shared.b16 {%0,%1}, [%2];"
                 : "=r"(r[0]), "=r"(r[1]) : "r"(addr));
}
__device__ __forceinline__ void mma16816(float* d, const unsigned* a,
                                         const unsigned* b) {
    asm volatile(
        "mma.sync.aligned.m16n8k16.row.col.f32.f16.f16.f32 "
        "{%0,%1,%2,%3}, {%4,%5,%6,%7}, {%8,%9}, {%0,%1,%2,%3};"
        : "+f"(d[0]), "+f"(d[1]), "+f"(d[2]), "+f"(d[3])
        : "r"(a[0]), "r"(a[1]), "r"(a[2]), "r"(a[3]), "r"(b[0]), "r"(b[1]));
}

__device__ __forceinline__ void split2(float2 f, unsigned& h, unsigned& l) {
    __half h0 = __float2half_rn(f.x), h1 = __float2half_rn(f.y);
    __half l0 = __float2half_rn(f.x - __half2float(h0));
    __half l1 = __float2half_rn(f.y - __half2float(h1));
    __half2 hp = __halves2half2(h0, h1), lp = __halves2half2(l0, l1);
    h = *(unsigned*)&hp;
    l = *(unsigned*)&lp;
}

// ---------------- CSR hist + rank capture + W convert side-job --------------
__global__ void hist_kernel(const void* __restrict__ ei, int e_cnt,
                            const float* __restrict__ W) {
    int is64 = block_detect_is64(ei);
    int t = threadIdx.x;
    int gid = blockIdx.x * 256 + t;
    if (gid < 128 * 128) {          // W1 -> hi/lo fp16 images (blocks 0-63)
        float w = W[gid];
        int k = gid >> 7, nn = gid & 127;
        __half hi = __float2half_rn(w);
        __half lo = __float2half_rn(w - __half2float(hi));
        g_W1h_hi[nn * 128 + k] = hi;
        g_W1h_lo[nn * 128 + k] = lo;
    }
    int base = blockIdx.x * 1024 + t;
    int d[4];
#pragma unroll
    for (int j = 0; j < 4; j++) {
        int i = base + j * 256;
        if (i < e_cnt) {
            d[j] = is64 ? (int)((const long long*)ei)[e_cnt + i]
                        : ((const int*)ei)[e_cnt + i];
        }
    }
#pragma unroll
    for (int j = 0; j < 4; j++) {
        int i = base + j * 256;
        if (i < e_cnt) g_rank[i] = atomicAdd(&g_deg[d[j]], 1);
    }
}

// ---------------- CSR scan: 4 items/thread, decoupled lookback --------------
__global__ void scan_kernel(int n, int tot) {
    __shared__ int warpsum[32];
    __shared__ int s_prev;
    int t = threadIdx.x, b = blockIdx.x;
    int lane = t & 31, wid = t >> 5;
    int base = (b * 1024 + t) * 4;
    int4 v = make_int4(0, 0, 0, 0);
    if (base + 3 < n) v = *(const int4*)&g_deg[base];
    else if (base < n) {
        v.x = g_deg[base];
        if (base + 1 < n) v.y = g_deg[base + 1];
        if (base + 2 < n) v.z = g_deg[base + 2];
    }
    int tsum = v.x + v.y + v.z + v.w;
    int x = tsum;
#pragma unroll
    for (int o = 1; o < 32; o <<= 1) {
        int y = __shfl_up_sync(0xffffffffu, x, o);
        if (lane >= o) x += y;
    }
    if (lane == 31) warpsum[wid] = x;
    __syncthreads();
    if (wid == 0) {
        int wv = warpsum[lane];
#pragma unroll
        for (int o = 1; o < 32; o <<= 1) {
            int y = __shfl_up_sync(0xffffffffu, wv, o);
            if (lane >= o) wv += y;
        }
        warpsum[lane] = wv;
    }
    __syncthreads();
    int incl = x + (wid ? warpsum[wid - 1] : 0);
    int agg = warpsum[31];

    if (b == 0) {
        if (t == 0) {
            *(volatile unsigned long long*)&g_scanpack[0] =
                (2ull << 32) | (unsigned)agg;
            s_prev = 0;
        }
    } else if (t < 32) {
        if (t == 0)
            *(volatile unsigned long long*)&g_scanpack[b] =
                (1ull << 32) | (unsigned)agg;
        __syncwarp();
        int sum = 0;
        int lb = b - 1;
        for (;;) {
            int j = lb - lane;
            unsigned long long w;
            unsigned f;
            for (;;) {
                w = (j >= 0) ? *(volatile unsigned long long*)&g_scanpack[j]
                             : (2ull << 32);
                f = (unsigned)(w >> 32);
                if (__all_sync(0xffffffffu, f != 0u)) break;
            }
            unsigned m2 = __ballot_sync(0xffffffffu, f == 2u);
            int fl = m2 ? (__ffs(m2) - 1) : 32;
            int take = (lane <= fl) ? (int)(unsigned)w : 0;
#pragma unroll
            for (int o = 16; o > 0; o >>= 1)
                take += __shfl_xor_sync(0xffffffffu, take, o);
            sum += take;
            if (m2) break;
            lb -= 32;
        }
        if (t == 0) {
            *(volatile unsigned long long*)&g_scanpack[b] =
                (2ull << 32) | (unsigned)(sum + agg);
            s_prev = sum;
        }
    }
    __syncthreads();
    if (base < n) {
        int r0 = s_prev + incl - tsum;
        int r1 = r0 + v.x, r2 = r1 + v.y, r3 = r2 + v.z;
        if (base + 3 < n) *(int4*)&g_rowptr[base] = make_int4(r0, r1, r2, r3);
        else {
            g_rowptr[base] = r0;
            if (base + 1 < n) g_rowptr[base + 1] = r1;
            if (base + 2 < n) g_rowptr[base + 2] = r2;
        }
    }
    if (b == 0 && t == 0) g_rowptr[n] = tot;
}

// ---------------- CSR scatter (rank-based, no atomics, 4-edge ILP) ----------
__global__ void scatter_kernel(const void* __restrict__ ei, int e_cnt) {
    int is64 = block_detect_is64(ei);
    int base = blockIdx.x * 1024 + threadIdx.x;
#pragma unroll
    for (int j = 0; j < 4; j++) {
        int i = base + j * 256;
        if (i < e_cnt) {
            int src, dst;
            edge_fetch(ei, e_cnt, i, is64, src, dst);
            g_esrc[g_rowptr[dst] + g_rank[i]] = src;
        }
    }
}

// ---------------- GEMM1 (HMMA split-fp16, reg-A) + fused att epilogue -------
#define BT 34816                       // 128 * 272 bytes
#define OFF_BH 0
#define OFF_BL BT
#define GEMM_SMEM (2 * BT)             // 69632

__global__ void __launch_bounds__(256, 2)
gemm1_kernel(const float* __restrict__ x,
             const float* __restrict__ att_s,
             const float* __restrict__ att_d, int n) {
    extern __shared__ char smc[];
    unsigned sbase = smem_u32(smc);
    int t = threadIdx.x, lane = t & 31, w = t >> 5;

    // B tiles: copy [n][k] fp16 images into padded smem rows
    {
        const uint4* bh = (const uint4*)g_W1h_hi;
        const uint4* bl = (const uint4*)g_W1h_lo;
#pragma unroll
        for (int i = 0; i < 8; i++) {
            int idx = t + i * 256;         // 0..2047 uint4s (16 per row)
            int row = idx >> 4, c8 = idx & 15;
            *(uint4*)(smc + OFF_BH + row * 272 + c8 * 16) = bh[idx];
            *(uint4*)(smc + OFF_BL + row * 272 + c8 * 16) = bl[idx];
        }
    }
    __syncthreads();

    int m0 = w * 16;
    int gr = lane >> 2, kc0 = (lane & 3) * 2;
    int r0 = blockIdx.x * 128 + m0 + gr;
    int r1 = r0 + 8;
    const float* xr0 = x + (size_t)r0 * 128;
    const float* xr1 = x + (size_t)r1 * 128;
    bool val0 = r0 < n, val1 = r1 < n;

    float acc[16][4];
#pragma unroll
    for (int nt = 0; nt < 16; nt++)
#pragma unroll
        for (int j = 0; j < 4; j++) acc[nt][j] = 0.f;

    unsigned bRow  = (unsigned)(lane & 7);
    unsigned bKoff = (unsigned)(((lane >> 3) & 1) * 8);
    const float2 fz = make_float2(0.f, 0.f);

    for (int kt = 0; kt < 8; kt++) {
        int kc = kt * 16 + kc0;
        // A fragments straight from gmem (mma m16n8k16 row-major A layout):
        // a0=(r0,k), a1=(r1,k), a2=(r0,k+8), a3=(r1,k+8)
        float2 f0 = val0 ? *(const float2*)(xr0 + kc)     : fz;
        float2 f1 = val1 ? *(const float2*)(xr1 + kc)     : fz;
        float2 f2 = val0 ? *(const float2*)(xr0 + kc + 8) : fz;
        float2 f3 = val1 ? *(const float2*)(xr1 + kc + 8) : fz;
        unsigned ah[4], al[4];
        split2(f0, ah[0], al[0]);
        split2(f1, ah[1], al[1]);
        split2(f2, ah[2], al[2]);
        split2(f3, ah[3], al[3]);
#pragma unroll
        for (int nt = 0; nt < 16; nt++) {
            unsigned bAddr = sbase + OFF_BH +
                (unsigned)((nt * 8 + bRow) * 272 + (kt * 16 + bKoff) * 2);
            unsigned bh[2], bl[2];
            ldsm_x2(bh, bAddr);
            ldsm_x2(bl, bAddr + BT);
            mma16816(acc[nt], ah, bh);
            mma16816(acc[nt], ah, bl);
            mma16816(acc[nt], al, bh);
        }
    }

    // Epilogue: thread holds rows r0, r1; cols nt*8 + 2*(lane%4) + {0,1}.
    {
        int c = lane & 3;
        float sv0[4] = {0, 0, 0, 0}, dv0[4] = {0, 0, 0, 0};
        float sv1[4] = {0, 0, 0, 0}, dv1[4] = {0, 0, 0, 0};
#pragma unroll
        for (int nt = 0; nt < 16; nt++) {
            int col = nt * 8 + 2 * c;
            float w0 = att_s[col], w1 = att_s[col + 1];
            float u0 = att_d[col], u1 = att_d[col + 1];
            int hd = nt >> 2;
            sv0[hd] += acc[nt][0] * w0 + acc[nt][1] * w1;
            dv0[hd] += acc[nt][0] * u0 + acc[nt][1] * u1;
            sv1[hd] += acc[nt][2] * w0 + acc[nt][3] * w1;
            dv1[hd] += acc[nt][2] * u0 + acc[nt][3] * u1;
            if (val0)
                g_h1h[(size_t)r0 * 64 + nt * 4 + c] =
                    __floats2half2_rn(acc[nt][0], acc[nt][1]);
            if (val1)
                g_h1h[(size_t)r1 * 64 + nt * 4 + c] =
                    __floats2half2_rn(acc[nt][2], acc[nt][3]);
        }
#pragma unroll
        for (int hd = 0; hd < 4; hd++) {
#pragma unroll
            for (int o = 1; o < 4; o <<= 1) {
                sv0[hd] += __shfl_xor_sync(0xffffffffu, sv0[hd], o);
                dv0[hd] += __shfl_xor_sync(0xffffffffu, dv0[hd], o);
                sv1[hd] += __shfl_xor_sync(0xffffffffu, sv1[hd], o);
                dv1[hd] += __shfl_xor_sync(0xffffffffu, dv1[hd], o);
            }
        }
        if (c == 0) {
#pragma unroll
            for (int hd = 0; hd < 4; hd++) {
                if (val0) {
                    g_as1[r0 * 4 + hd] = sv0[hd];
                    g_ad1[r0 * 4 + hd] = dv0[hd];
                }
                if (val1) {
                    g_as1[r1 * 4 + hd] = sv1[hd];
                    g_ad1[r1 * 4 + hd] = dv1[hd];
                }
            }
        }
    }
}

// ---------------- layer-1 aggregation (CSR, warp per dst; self-loop fused) --
__global__ void agg1_kernel(const float* __restrict__ b1,
                            const float* __restrict__ W2, int n) {
    int v = (blockIdx.x * blockDim.x + threadIdx.x) >> 5;
    int lane = threadIdx.x & 31;
    if (v >= n) return;
    int hd = lane >> 3;
    int beg = g_rowptr[v];
    int end = g_rowptr[v + 1];
    float adv = g_ad1[v * 4 + hd];
    const uint2* H2 = (const uint2*)g_h1h;

    // self-loop contribution (exact: loops were excluded from the CSR)
    float4 acc;
    float den;
    {
        float exs = __expf(lrelu(g_as1[v * 4 + hd] + adv));
        uint2 pv = H2[v * 32 + lane];
        float2 q0 = __half22float2(*(__half2*)&pv.x);
        float2 q1 = __half22float2(*(__half2*)&pv.y);
        den = exs;
        acc = make_float4(q0.x * exs, q0.y * exs, q1.x * exs, q1.y * exs);
    }

    int e = beg;
    for (; e + 3 < end; e += 4) {
        int s0 = g_esrc[e], s1 = g_esrc[e + 1];
        int s2 = g_esrc[e + 2], s3 = g_esrc[e + 3];
        float a0 = g_as1[s0 * 4 + hd], a1 = g_as1[s1 * 4 + hd];
        float a2 = g_as1[s2 * 4 + hd], a3 = g_as1[s3 * 4 + hd];
        uint2 p0 = H2[s0 * 32 + lane], p1 = H2[s1 * 32 + lane];
        uint2 p2 = H2[s2 * 32 + lane], p3 = H2[s3 * 32 + lane];
        float e0 = __expf(lrelu(a0 + adv)), e1 = __expf(lrelu(a1 + adv));
        float e2 = __expf(lrelu(a2 + adv)), e3 = __expf(lrelu(a3 + adv));
        den += (e0 + e1) + (e2 + e3);
        float2 q;
        q = __half22float2(*(__half2*)&p0.x); acc.x += q.x * e0; acc.y += q.y * e0;
        q = __half22float2(*(__half2*)&p0.y); acc.z += q.x * e0; acc.w += q.y * e0;
        q = __half22float2(*(__half2*)&p1.x); acc.x += q.x * e1; acc.y += q.y * e1;
        q = __half22float2(*(__half2*)&p1.y); acc.z += q.x * e1; acc.w += q.y * e1;
        q = __half22float2(*(__half2*)&p2.x); acc.x += q.x * e2; acc.y += q.y * e2;
        q = __half22float2(*(__half2*)&p2.y); acc.z += q.x * e2; acc.w += q.y * e2;
        q = __half22float2(*(__half2*)&p3.x); acc.x += q.x * e3; acc.y += q.y * e3;
        q = __half22float2(*(__half2*)&p3.y); acc.z += q.x * e3; acc.w += q.y * e3;
    }
    for (; e < end; e++) {
        int s0 = g_esrc[e];
        float e0 = __expf(lrelu(g_as1[s0 * 4 + hd] + adv));
        uint2 p0 = H2[s0 * 32 + lane];
        float2 q;
        den += e0;
        q = __half22float2(*(__half2*)&p0.x); acc.x += q.x * e0; acc.y += q.y * e0;
        q = __half22float2(*(__half2*)&p0.y); acc.z += q.x * e0; acc.w += q.y * e0;
    }

    float inv = 1.f / (den + 1e-16f);
    float4 bb = ((const float4*)b1)[lane];
    float4 w  = ((const float4*)W2)[lane];
    float x0 = fmaxf(acc.x * inv + bb.x, 0.f);
    float x1 = fmaxf(acc.y * inv + bb.y, 0.f);
    float x2 = fmaxf(acc.z * inv + bb.z, 0.f);
    float x3 = fmaxf(acc.w * inv + bb.w, 0.f);
    float s = x0 * w.x + x1 * w.y + x2 * w.z + x3 * w.w;
#pragma unroll
    for (int o = 16; o > 0; o >>= 1) s += __shfl_xor_sync(0xffffffffu, s, o);
    if (lane == 0) g_h2[v] = s;
}

// ---------------- layer-2 aggregation (CSR, thread per dst; self-loop fused) -
__global__ void agg2_kernel(const float* __restrict__ att_s2,
                            const float* __restrict__ att_d2,
                            const float* __restrict__ b2,
                            float* __restrict__ out, int n) {
    int v = blockIdx.x * blockDim.x + threadIdx.x;
    if (v >= n) return;
    float as2 = att_s2[0];
    float hv = g_h2[v];
    float adv = hv * att_d2[0];
    int beg = g_rowptr[v];
    int end = g_rowptr[v + 1];
    float exs = __expf(lrelu(hv * as2 + adv));
    float den = exs, num = hv * exs;
    int e = beg;
    for (; e + 3 < end; e += 4) {
        int s0 = g_esrc[e], s1 = g_esrc[e + 1];
        int s2 = g_esrc[e + 2], s3 = g_esrc[e + 3];
        float h0 = g_h2[s0], h1 = g_h2[s1], h2 = g_h2[s2], h3 = g_h2[s3];
        float e0 = __expf(lrelu(h0 * as2 + adv));
        float e1 = __expf(lrelu(h1 * as2 + adv));
        float e2 = __expf(lrelu(h2 * as2 + adv));
        float e3 = __expf(lrelu(h3 * as2 + adv));
        den += (e0 + e1) + (e2 + e3);
        num += (h0 * e0 + h1 * e1) + (h2 * e2 + h3 * e3);
    }
    for (; e < end; e++) {
        float h0 = g_h2[g_esrc[e]];
        float e0 = __expf(lrelu(h0 * as2 + adv));
        den += e0;
        num += h0 * e0;
    }
    out[v] = num / (den + 1e-16f) + b2[0];
}

// ---------------- launch ------------------------------------------------------
extern "C" void kernel_launch(void* const* d_in, const int* in_sizes, int n_in,
                              void* d_out, int out_size) {
    const float* x        = (const float*)d_in[0];
    const void*  ei       = d_in[1];
    const float* W1       = (const float*)d_in[2];
    const float* att_src1 = (const float*)d_in[3];
    const float* att_dst1 = (const float*)d_in[4];
    const float* b1       = (const float*)d_in[5];
    const float* W2       = (const float*)d_in[6];
    const float* att_src2 = (const float*)d_in[7];
    const float* att_dst2 = (const float*)d_in[8];
    const float* b2       = (const float*)d_in[9];
    float* out = (float*)d_out;

    int n = in_sizes[0] / 128;
    int e = in_sizes[1] / 2;
    int nb = (n + 4095) / 4096;

    void *p_deg, *p_pack;
    cudaGetSymbolAddress(&p_deg, g_deg);
    cudaGetSymbolAddress(&p_pack, g_scanpack);
    cudaMemsetAsync(p_deg, 0, (size_t)n * sizeof(int));
    cudaMemsetAsync(p_pack, 0, 128 * sizeof(unsigned long long));

    cudaFuncSetAttribute(gemm1_kernel,
                         cudaFuncAttributeMaxDynamicSharedMemorySize, GEMM_SMEM);

    hist_kernel<<<(e + 1023) / 1024, 256>>>(ei, e, W1);
    gemm1_kernel<<<(n + 127) / 128, 256, GEMM_SMEM>>>(x, att_src1, att_dst1, n);
    scan_kernel<<<nb, 1024>>>(n, e);
    scatter_kernel<<<(e + 1023) / 1024, 256>>>(ei, e);
    agg1_kernel<<<(n + 7) / 8, 256>>>(b1, W2, n);
    agg2_kernel<<<(n + 255) / 256, 256>>>(att_src2, att_dst2, b2, out, n);
}

// round 11
// speedup vs baseline: 1.2493x; 1.0691x over previous
#include <cuda_runtime.h>
#include <cuda_fp16.h>

#define MAXN 100000
#define MAXE 1600000

// ---------------- scratch (device globals; no allocations allowed) ----------
__device__ __align__(16) __half2  g_h1h[MAXN * 64];   // h1 fp16, 128 ch/row
__device__ __align__(16) float    g_as1[MAXN * 4];
__device__ __align__(16) float    g_ad1[MAXN * 4];
__device__ float                  g_h2[MAXN];
__device__ __align__(16) int g_deg[MAXN];             // zeroed by scatter epilogue
__device__ __align__(16) int g_rowptr[MAXN + 4];
__device__ int g_rank[MAXE];
__device__ int g_esrc[MAXE];
__device__ unsigned long long g_scanpack[128];        // (flag<<32)|value

__device__ __forceinline__ float lrelu(float v) { return v > 0.f ? v : 0.2f * v; }

__device__ __forceinline__ void edge_fetch(const void* ei, int e_cnt, int i,
                                           int is64, int& src, int& dst) {
    if (is64) {
        const long long* p = (const long long*)ei;
        src = (int)p[i];
        dst = (int)p[e_cnt + i];
    } else {
        const int* p = (const int*)ei;
        src = p[i];
        dst = p[e_cnt + i];
    }
}

// per-block dtype detection: int64 iff first 32 high-words are all zero
__device__ __forceinline__ int block_detect_is64(const void* ei) {
    __shared__ int s_is64;
    if (threadIdx.x < 32) {
        unsigned hw = ((const unsigned*)ei)[2 * threadIdx.x + 1];
        unsigned nz = __ballot_sync(0xffffffffu, hw != 0u);
        if (threadIdx.x == 0) s_is64 = (nz == 0u) ? 1 : 0;
    }
    __syncthreads();
    return s_is64;
}

__device__ __forceinline__ unsigned smem_u32(const void* p) {
    unsigned a;
    asm("{ .reg .u64 t; cvta.to.shared.u64 t, %1; cvt.u32.u64 %0, t; }"
        : "=r"(a) : "l"(p));
    return a;
}

__device__ __forceinline__ void ldsm_x2(unsigned* r, unsigned addr) {
    asm volatile("ldmatrix.sync.aligned.m8n8.x2.shared.b16 {%0,%1}, [%2];"
                 : "=r"(r[0]), "=r"(r[1]) : "r"(addr));
}
__device__ __forceinline__ void mma16816(float* d, const unsigned* a,
                                         const unsigned* b) {
    asm volatile(
        "mma.sync.aligned.m16n8k16.row.col.f32.f16.f16.f32 "
        "{%0,%1,%2,%3}, {%4,%5,%6,%7}, {%8,%9}, {%0,%1,%2,%3};"
        : "+f"(d[0]), "+f"(d[1]), "+f"(d[2]), "+f"(d[3])
        : "r"(a[0]), "r"(a[1]), "r"(a[2]), "r"(a[3]), "r"(b[0]), "r"(b[1]));
}

__device__ __forceinline__ void split2(float2 f, unsigned& h, unsigned& l) {
    __half h0 = __float2half_rn(f.x), h1 = __float2half_rn(f.y);
    __half l0 = __float2half_rn(f.x - __half2float(h0));
    __half l1 = __float2half_rn(f.y - __half2float(h1));
    __half2 hp = __halves2half2(h0, h1), lp = __halves2half2(l0, l1);
    h = *(unsigned*)&hp;
    l = *(unsigned*)&lp;
}

// ---------------- fused GEMM1 + CSR hist (block-partitioned) ----------------
// Blocks [0, gb): HMMA split-fp16 GEMM (W converted in-block) + att epilogue.
// Blocks [gb, ..): edge histogram + rank capture (4-edge ILP).
#define BT 34816                       // 128 * 272 bytes
#define OFF_BH 0
#define OFF_BL BT
#define GEMM_SMEM (2 * BT)             // 69632

__global__ void __launch_bounds__(256, 2)
fused_gemm_hist_kernel(const float* __restrict__ x,
                       const float* __restrict__ W,
                       const float* __restrict__ att_s,
                       const float* __restrict__ att_d, int n, int gb,
                       const void* __restrict__ ei, int e_cnt) {
    int t = threadIdx.x;

    if (blockIdx.x >= gb) {
        // ---------------- hist path ----------------
        int is64 = block_detect_is64(ei);
        int base = (blockIdx.x - gb) * 1024 + t;
        int d[4];
#pragma unroll
        for (int j = 0; j < 4; j++) {
            int i = base + j * 256;
            if (i < e_cnt) {
                d[j] = is64 ? (int)((const long long*)ei)[e_cnt + i]
                            : ((const int*)ei)[e_cnt + i];
            }
        }
#pragma unroll
        for (int j = 0; j < 4; j++) {
            int i = base + j * 256;
            if (i < e_cnt) g_rank[i] = atomicAdd(&g_deg[d[j]], 1);
        }
        return;
    }

    // ---------------- GEMM path ----------------
    extern __shared__ char smc[];
    unsigned sbase = smem_u32(smc);
    int lane = t & 31, w = t >> 5;

    // Convert W1 (fp32 [k][n]) -> hi/lo fp16 B tiles ([n][k], padded rows)
    {
        int nn = t & 127;
        int kb = (t >> 7) * 64;           // 0 or 64
#pragma unroll 8
        for (int kk = kb; kk < kb + 64; kk += 2) {
            float w0 = W[kk * 128 + nn];
            float w1 = W[(kk + 1) * 128 + nn];
            __half h0 = __float2half_rn(w0), h1 = __float2half_rn(w1);
            __half l0 = __float2half_rn(w0 - __half2float(h0));
            __half l1 = __float2half_rn(w1 - __half2float(h1));
            __half2 hp = __halves2half2(h0, h1);
            __half2 lp = __halves2half2(l0, l1);
            *(__half2*)(smc + OFF_BH + nn * 272 + kk * 2) = hp;
            *(__half2*)(smc + OFF_BL + nn * 272 + kk * 2) = lp;
        }
    }
    __syncthreads();

    int m0 = w * 16;
    int gr = lane >> 2, kc0 = (lane & 3) * 2;
    int r0 = blockIdx.x * 128 + m0 + gr;
    int r1 = r0 + 8;
    const float* xr0 = x + (size_t)r0 * 128;
    const float* xr1 = x + (size_t)r1 * 128;
    bool val0 = r0 < n, val1 = r1 < n;

    float acc[16][4];
#pragma unroll
    for (int nt = 0; nt < 16; nt++)
#pragma unroll
        for (int j = 0; j < 4; j++) acc[nt][j] = 0.f;

    unsigned bRow  = (unsigned)(lane & 7);
    unsigned bKoff = (unsigned)(((lane >> 3) & 1) * 8);
    const float2 fz = make_float2(0.f, 0.f);

    for (int kt = 0; kt < 8; kt++) {
        int kc = kt * 16 + kc0;
        float2 f0 = val0 ? *(const float2*)(xr0 + kc)     : fz;
        float2 f1 = val1 ? *(const float2*)(xr1 + kc)     : fz;
        float2 f2 = val0 ? *(const float2*)(xr0 + kc + 8) : fz;
        float2 f3 = val1 ? *(const float2*)(xr1 + kc + 8) : fz;
        unsigned ah[4], al[4];
        split2(f0, ah[0], al[0]);
        split2(f1, ah[1], al[1]);
        split2(f2, ah[2], al[2]);
        split2(f3, ah[3], al[3]);
#pragma unroll
        for (int nt = 0; nt < 16; nt++) {
            unsigned bAddr = sbase + OFF_BH +
                (unsigned)((nt * 8 + bRow) * 272 + (kt * 16 + bKoff) * 2);
            unsigned bh[2], bl[2];
            ldsm_x2(bh, bAddr);
            ldsm_x2(bl, bAddr + BT);
            mma16816(acc[nt], ah, bh);
            mma16816(acc[nt], ah, bl);
            mma16816(acc[nt], al, bh);
        }
    }

    // Epilogue: thread holds rows r0, r1; cols nt*8 + 2*(lane%4) + {0,1}.
    {
        int c = lane & 3;
        float sv0[4] = {0, 0, 0, 0}, dv0[4] = {0, 0, 0, 0};
        float sv1[4] = {0, 0, 0, 0}, dv1[4] = {0, 0, 0, 0};
#pragma unroll
        for (int nt = 0; nt < 16; nt++) {
            int col = nt * 8 + 2 * c;
            float w0 = att_s[col], w1 = att_s[col + 1];
            float u0 = att_d[col], u1 = att_d[col + 1];
            int hd = nt >> 2;
            sv0[hd] += acc[nt][0] * w0 + acc[nt][1] * w1;
            dv0[hd] += acc[nt][0] * u0 + acc[nt][1] * u1;
            sv1[hd] += acc[nt][2] * w0 + acc[nt][3] * w1;
            dv1[hd] += acc[nt][2] * u0 + acc[nt][3] * u1;
            if (val0)
                g_h1h[(size_t)r0 * 64 + nt * 4 + c] =
                    __floats2half2_rn(acc[nt][0], acc[nt][1]);
            if (val1)
                g_h1h[(size_t)r1 * 64 + nt * 4 + c] =
                    __floats2half2_rn(acc[nt][2], acc[nt][3]);
        }
#pragma unroll
        for (int hd = 0; hd < 4; hd++) {
#pragma unroll
            for (int o = 1; o < 4; o <<= 1) {
                sv0[hd] += __shfl_xor_sync(0xffffffffu, sv0[hd], o);
                dv0[hd] += __shfl_xor_sync(0xffffffffu, dv0[hd], o);
                sv1[hd] += __shfl_xor_sync(0xffffffffu, sv1[hd], o);
                dv1[hd] += __shfl_xor_sync(0xffffffffu, dv1[hd], o);
            }
        }
        if (c == 0) {
#pragma unroll
            for (int hd = 0; hd < 4; hd++) {
                if (val0) {
                    g_as1[r0 * 4 + hd] = sv0[hd];
                    g_ad1[r0 * 4 + hd] = dv0[hd];
                }
                if (val1) {
                    g_as1[r1 * 4 + hd] = sv1[hd];
                    g_ad1[r1 * 4 + hd] = dv1[hd];
                }
            }
        }
    }
}

// ---------------- CSR scan: 4 items/thread, decoupled lookback --------------
__global__ void scan_kernel(int n, int tot) {
    __shared__ int warpsum[32];
    __shared__ int s_prev;
    int t = threadIdx.x, b = blockIdx.x;
    int lane = t & 31, wid = t >> 5;
    int base = (b * 1024 + t) * 4;
    int4 v = make_int4(0, 0, 0, 0);
    if (base + 3 < n) v = *(const int4*)&g_deg[base];
    else if (base < n) {
        v.x = g_deg[base];
        if (base + 1 < n) v.y = g_deg[base + 1];
        if (base + 2 < n) v.z = g_deg[base + 2];
    }
    int tsum = v.x + v.y + v.z + v.w;
    int x = tsum;
#pragma unroll
    for (int o = 1; o < 32; o <<= 1) {
        int y = __shfl_up_sync(0xffffffffu, x, o);
        if (lane >= o) x += y;
    }
    if (lane == 31) warpsum[wid] = x;
    __syncthreads();
    if (wid == 0) {
        int wv = warpsum[lane];
#pragma unroll
        for (int o = 1; o < 32; o <<= 1) {
            int y = __shfl_up_sync(0xffffffffu, wv, o);
            if (lane >= o) wv += y;
        }
        warpsum[lane] = wv;
    }
    __syncthreads();
    int incl = x + (wid ? warpsum[wid - 1] : 0);
    int agg = warpsum[31];

    if (b == 0) {
        if (t == 0) {
            *(volatile unsigned long long*)&g_scanpack[0] =
                (2ull << 32) | (unsigned)agg;
            s_prev = 0;
        }
    } else if (t < 32) {
        if (t == 0)
            *(volatile unsigned long long*)&g_scanpack[b] =
                (1ull << 32) | (unsigned)agg;
        __syncwarp();
        int sum = 0;
        int lb = b - 1;
        for (;;) {
            int j = lb - lane;
            unsigned long long w;
            unsigned f;
            for (;;) {
                w = (j >= 0) ? *(volatile unsigned long long*)&g_scanpack[j]
                             : (2ull << 32);
                f = (unsigned)(w >> 32);
                if (__all_sync(0xffffffffu, f != 0u)) break;
            }
            unsigned m2 = __ballot_sync(0xffffffffu, f == 2u);
            int fl = m2 ? (__ffs(m2) - 1) : 32;
            int take = (lane <= fl) ? (int)(unsigned)w : 0;
#pragma unroll
            for (int o = 16; o > 0; o >>= 1)
                take += __shfl_xor_sync(0xffffffffu, take, o);
            sum += take;
            if (m2) break;
            lb -= 32;
        }
        if (t == 0) {
            *(volatile unsigned long long*)&g_scanpack[b] =
                (2ull << 32) | (unsigned)(sum + agg);
            s_prev = sum;
        }
    }
    __syncthreads();
    if (base < n) {
        int r0 = s_prev + incl - tsum;
        int r1 = r0 + v.x, r2 = r1 + v.y, r3 = r2 + v.z;
        if (base + 3 < n) *(int4*)&g_rowptr[base] = make_int4(r0, r1, r2, r3);
        else {
            g_rowptr[base] = r0;
            if (base + 1 < n) g_rowptr[base + 1] = r1;
            if (base + 2 < n) g_rowptr[base + 2] = r2;
        }
    }
    if (b == 0 && t == 0) g_rowptr[n] = tot;
}

// -------- CSR scatter (rank-based, no atomics) + scratch self-clean ---------
__global__ void scatter_kernel(const void* __restrict__ ei, int e_cnt, int n) {
    int is64 = block_detect_is64(ei);
    int base = blockIdx.x * 1024 + threadIdx.x;
#pragma unroll
    for (int j = 0; j < 4; j++) {
        int i = base + j * 256;
        if (i < e_cnt) {
            int src, dst;
            edge_fetch(ei, e_cnt, i, is64, src, dst);
            g_esrc[g_rowptr[dst] + g_rank[i]] = src;
        }
    }
    // reset scratch for the next graph replay (deg/scanpack are dead here)
    int gid = blockIdx.x * 256 + threadIdx.x;
    if (gid < n) g_deg[gid] = 0;
    if (gid < 128) g_scanpack[gid] = 0ull;
}

// ---------------- layer-1 aggregation (CSR, warp per dst; self-loop fused) --
__global__ void agg1_kernel(const float* __restrict__ b1,
                            const float* __restrict__ W2, int n) {
    int v = (blockIdx.x * blockDim.x + threadIdx.x) >> 5;
    int lane = threadIdx.x & 31;
    if (v >= n) return;
    int hd = lane >> 3;
    int beg = g_rowptr[v];
    int end = g_rowptr[v + 1];
    float adv = g_ad1[v * 4 + hd];
    const uint2* H2 = (const uint2*)g_h1h;

    // self-loop contribution (exact: loops were excluded from the CSR)
    float4 acc;
    float den;
    {
        float exs = __expf(lrelu(g_as1[v * 4 + hd] + adv));
        uint2 pv = H2[v * 32 + lane];
        float2 q0 = __half22float2(*(__half2*)&pv.x);
        float2 q1 = __half22float2(*(__half2*)&pv.y);
        den = exs;
        acc = make_float4(q0.x * exs, q0.y * exs, q1.x * exs, q1.y * exs);
    }

    int e = beg;
    for (; e + 3 < end; e += 4) {
        int s0 = g_esrc[e], s1 = g_esrc[e + 1];
        int s2 = g_esrc[e + 2], s3 = g_esrc[e + 3];
        float a0 = g_as1[s0 * 4 + hd], a1 = g_as1[s1 * 4 + hd];
        float a2 = g_as1[s2 * 4 + hd], a3 = g_as1[s3 * 4 + hd];
        uint2 p0 = H2[s0 * 32 + lane], p1 = H2[s1 * 32 + lane];
        uint2 p2 = H2[s2 * 32 + lane], p3 = H2[s3 * 32 + lane];
        float e0 = __expf(lrelu(a0 + adv)), e1 = __expf(lrelu(a1 + adv));
        float e2 = __expf(lrelu(a2 + adv)), e3 = __expf(lrelu(a3 + adv));
        den += (e0 + e1) + (e2 + e3);
        float2 q;
        q = __half22float2(*(__half2*)&p0.x); acc.x += q.x * e0; acc.y += q.y * e0;
        q = __half22float2(*(__half2*)&p0.y); acc.z += q.x * e0; acc.w += q.y * e0;
        q = __half22float2(*(__half2*)&p1.x); acc.x += q.x * e1; acc.y += q.y * e1;
        q = __half22float2(*(__half2*)&p1.y); acc.z += q.x * e1; acc.w += q.y * e1;
        q = __half22float2(*(__half2*)&p2.x); acc.x += q.x * e2; acc.y += q.y * e2;
        q = __half22float2(*(__half2*)&p2.y); acc.z += q.x * e2; acc.w += q.y * e2;
        q = __half22float2(*(__half2*)&p3.x); acc.x += q.x * e3; acc.y += q.y * e3;
        q = __half22float2(*(__half2*)&p3.y); acc.z += q.x * e3; acc.w += q.y * e3;
    }
    for (; e < end; e++) {
        int s0 = g_esrc[e];
        float e0 = __expf(lrelu(g_as1[s0 * 4 + hd] + adv));
        uint2 p0 = H2[s0 * 32 + lane];
        float2 q;
        den += e0;
        q = __half22float2(*(__half2*)&p0.x); acc.x += q.x * e0; acc.y += q.y * e0;
        q = __half22float2(*(__half2*)&p0.y); acc.z += q.x * e0; acc.w += q.y * e0;
    }

    float inv = 1.f / (den + 1e-16f);
    float4 bb = ((const float4*)b1)[lane];
    float4 w  = ((const float4*)W2)[lane];
    float x0 = fmaxf(acc.x * inv + bb.x, 0.f);
    float x1 = fmaxf(acc.y * inv + bb.y, 0.f);
    float x2 = fmaxf(acc.z * inv + bb.z, 0.f);
    float x3 = fmaxf(acc.w * inv + bb.w, 0.f);
    float s = x0 * w.x + x1 * w.y + x2 * w.z + x3 * w.w;
#pragma unroll
    for (int o = 16; o > 0; o >>= 1) s += __shfl_xor_sync(0xffffffffu, s, o);
    if (lane == 0) g_h2[v] = s;
}

// -------- layer-2 aggregation (4 lanes per dst node; self-loop fused) -------
__global__ void agg2_kernel(const float* __restrict__ att_s2,
                            const float* __restrict__ att_d2,
                            const float* __restrict__ b2,
                            float* __restrict__ out, int n) {
    int tid = blockIdx.x * blockDim.x + threadIdx.x;
    int v = tid >> 2;
    int sub = tid & 3;
    bool valid = v < n;
    int vv = valid ? v : 0;
    float as2 = att_s2[0];
    float hv = g_h2[vv];
    float adv = hv * att_d2[0];
    int beg = g_rowptr[vv];
    int end = valid ? g_rowptr[vv + 1] : beg;
    float den = 0.f, num = 0.f;
    if (sub == 0 && valid) {
        float exs = __expf(lrelu(hv * as2 + adv));
        den = exs;
        num = hv * exs;
    }
    int e = beg + sub;
    for (; e + 4 < end; e += 8) {
        float h0 = g_h2[g_esrc[e]];
        float h1 = g_h2[g_esrc[e + 4]];
        float e0 = __expf(lrelu(h0 * as2 + adv));
        float e1 = __expf(lrelu(h1 * as2 + adv));
        den += e0 + e1;
        num += h0 * e0 + h1 * e1;
    }
    if (e < end) {
        float h0 = g_h2[g_esrc[e]];
        float e0 = __expf(lrelu(h0 * as2 + adv));
        den += e0;
        num += h0 * e0;
    }
    den += __shfl_xor_sync(0xffffffffu, den, 1);
    num += __shfl_xor_sync(0xffffffffu, num, 1);
    den += __shfl_xor_sync(0xffffffffu, den, 2);
    num += __shfl_xor_sync(0xffffffffu, num, 2);
    if (valid && sub == 0) out[v] = num / (den + 1e-16f) + b2[0];
}

// ---------------- launch ------------------------------------------------------
extern "C" void kernel_launch(void* const* d_in, const int* in_sizes, int n_in,
                              void* d_out, int out_size) {
    const float* x        = (const float*)d_in[0];
    const void*  ei       = d_in[1];
    const float* W1       = (const float*)d_in[2];
    const float* att_src1 = (const float*)d_in[3];
    const float* att_dst1 = (const float*)d_in[4];
    const float* b1       = (const float*)d_in[5];
    const float* W2       = (const float*)d_in[6];
    const float* att_src2 = (const float*)d_in[7];
    const float* att_dst2 = (const float*)d_in[8];
    const float* b2       = (const float*)d_in[9];
    float* out = (float*)d_out;

    int n = in_sizes[0] / 128;
    int e = in_sizes[1] / 2;
    int nb = (n + 4095) / 4096;
    int gb = (n + 127) / 128;
    int hb = (e + 1023) / 1024;

    cudaFuncSetAttribute(fused_gemm_hist_kernel,
                         cudaFuncAttributeMaxDynamicSharedMemorySize, GEMM_SMEM);

    fused_gemm_hist_kernel<<<gb + hb, 256, GEMM_SMEM>>>(
        x, W1, att_src1, att_dst1, n, gb, ei, e);
    scan_kernel<<<nb, 1024>>>(n, e);
    scatter_kernel<<<hb, 256>>>(ei, e, n);
    agg1_kernel<<<(n + 7) / 8, 256>>>(b1, W2, n);
    agg2_kernel<<<(4 * n + 255) / 256, 256>>>(att_src2, att_dst2, b2, out, n);
}

// round 12
// speedup vs baseline: 1.2748x; 1.0204x over previous
#include <cuda_runtime.h>
#include <cuda_fp16.h>

#define MAXN 100000
#define MAXE 1600000
#define LOG2E 1.4426950408889634f

// ---------------- scratch (device globals; no allocations allowed) ----------
__device__ __align__(16) __half2  g_h1h[MAXN * 64];   // h1 fp16, 128 ch/row
__device__ __align__(16) float    g_as1[MAXN * 4];    // pre-scaled by log2(e)
__device__ __align__(16) float    g_ad1[MAXN * 4];    // pre-scaled by log2(e)
__device__ float                  g_h2[MAXN];
__device__ __align__(16) int g_deg[MAXN];             // zeroed by scatter epilogue
__device__ __align__(16) int g_rowptr[MAXN + 4];
__device__ int g_rank[MAXE];
__device__ int g_esrc[MAXE];
__device__ unsigned long long g_scanpack[128];        // (flag<<32)|value

__device__ __forceinline__ float ex2(float a) {
    float r;
    asm("ex2.approx.f32 %0, %1;" : "=f"(r) : "f"(a));
    return r;
}
// exp(lrelu(x)) with x pre-scaled by log2e: lrelu commutes with positive scale
__device__ __forceinline__ float exp_lrelu(float a) {
    return ex2(fmaxf(a, 0.2f * a));
}

__device__ __forceinline__ void edge_fetch(const void* ei, int e_cnt, int i,
                                           int is64, int& src, int& dst) {
    if (is64) {
        const long long* p = (const long long*)ei;
        src = (int)p[i];
        dst = (int)p[e_cnt + i];
    } else {
        const int* p = (const int*)ei;
        src = p[i];
        dst = p[e_cnt + i];
    }
}

// per-block dtype detection: int64 iff first 32 high-words are all zero
__device__ __forceinline__ int block_detect_is64(const void* ei) {
    __shared__ int s_is64;
    if (threadIdx.x < 32) {
        unsigned hw = ((const unsigned*)ei)[2 * threadIdx.x + 1];
        unsigned nz = __ballot_sync(0xffffffffu, hw != 0u);
        if (threadIdx.x == 0) s_is64 = (nz == 0u) ? 1 : 0;
    }
    __syncthreads();
    return s_is64;
}

__device__ __forceinline__ unsigned smem_u32(const void* p) {
    unsigned a;
    asm("{ .reg .u64 t; cvta.to.shared.u64 t, %1; cvt.u32.u64 %0, t; }"
        : "=r"(a) : "l"(p));
    return a;
}

__device__ __forceinline__ void ldsm_x2(unsigned* r, unsigned addr) {
    asm volatile("ldmatrix.sync.aligned.m8n8.x2.shared.b16 {%0,%1}, [%2];"
                 : "=r"(r[0]), "=r"(r[1]) : "r"(addr));
}
__device__ __forceinline__ void mma16816(float* d, const unsigned* a,
                                         const unsigned* b) {
    asm volatile(
        "mma.sync.aligned.m16n8k16.row.col.f32.f16.f16.f32 "
        "{%0,%1,%2,%3}, {%4,%5,%6,%7}, {%8,%9}, {%0,%1,%2,%3};"
        : "+f"(d[0]), "+f"(d[1]), "+f"(d[2]), "+f"(d[3])
        : "r"(a[0]), "r"(a[1]), "r"(a[2]), "r"(a[3]), "r"(b[0]), "r"(b[1]));
}

__device__ __forceinline__ void split2(float2 f, unsigned& h, unsigned& l) {
    __half h0 = __float2half_rn(f.x), h1 = __float2half_rn(f.y);
    __half l0 = __float2half_rn(f.x - __half2float(h0));
    __half l1 = __float2half_rn(f.y - __half2float(h1));
    __half2 hp = __halves2half2(h0, h1), lp = __halves2half2(l0, l1);
    h = *(unsigned*)&hp;
    l = *(unsigned*)&lp;
}

// ---------------- fused GEMM1 + CSR hist (block-partitioned) ----------------
#define BT 34816                       // 128 * 272 bytes
#define OFF_BH 0
#define OFF_BL BT
#define GEMM_SMEM (2 * BT)             // 69632

__global__ void __launch_bounds__(256, 2)
fused_gemm_hist_kernel(const float* __restrict__ x,
                       const float* __restrict__ W,
                       const float* __restrict__ att_s,
                       const float* __restrict__ att_d, int n, int gb,
                       const void* __restrict__ ei, int e_cnt) {
    int t = threadIdx.x;

    if (blockIdx.x >= gb) {
        // ---------------- hist path ----------------
        int is64 = block_detect_is64(ei);
        int base = (blockIdx.x - gb) * 1024 + t;
        int d[4];
#pragma unroll
        for (int j = 0; j < 4; j++) {
            int i = base + j * 256;
            if (i < e_cnt) {
                d[j] = is64 ? (int)((const long long*)ei)[e_cnt + i]
                            : ((const int*)ei)[e_cnt + i];
            }
        }
#pragma unroll
        for (int j = 0; j < 4; j++) {
            int i = base + j * 256;
            if (i < e_cnt) g_rank[i] = atomicAdd(&g_deg[d[j]], 1);
        }
        return;
    }

    // ---------------- GEMM path ----------------
    extern __shared__ char smc[];
    unsigned sbase = smem_u32(smc);
    int lane = t & 31, w = t >> 5;

    // Convert W1 (fp32 [k][n]) -> hi/lo fp16 B tiles ([n][k], padded rows)
    {
        int nn = t & 127;
        int kb = (t >> 7) * 64;           // 0 or 64
#pragma unroll 8
        for (int kk = kb; kk < kb + 64; kk += 2) {
            float w0 = W[kk * 128 + nn];
            float w1 = W[(kk + 1) * 128 + nn];
            __half h0 = __float2half_rn(w0), h1 = __float2half_rn(w1);
            __half l0 = __float2half_rn(w0 - __half2float(h0));
            __half l1 = __float2half_rn(w1 - __half2float(h1));
            __half2 hp = __halves2half2(h0, h1);
            __half2 lp = __halves2half2(l0, l1);
            *(__half2*)(smc + OFF_BH + nn * 272 + kk * 2) = hp;
            *(__half2*)(smc + OFF_BL + nn * 272 + kk * 2) = lp;
        }
    }
    __syncthreads();

    int m0 = w * 16;
    int gr = lane >> 2, kc0 = (lane & 3) * 2;
    int r0 = blockIdx.x * 128 + m0 + gr;
    int r1 = r0 + 8;
    const float* xr0 = x + (size_t)r0 * 128;
    const float* xr1 = x + (size_t)r1 * 128;
    bool val0 = r0 < n, val1 = r1 < n;

    float acc[16][4];
#pragma unroll
    for (int nt = 0; nt < 16; nt++)
#pragma unroll
        for (int j = 0; j < 4; j++) acc[nt][j] = 0.f;

    unsigned bRow  = (unsigned)(lane & 7);
    unsigned bKoff = (unsigned)(((lane >> 3) & 1) * 8);
    const float2 fz = make_float2(0.f, 0.f);

    for (int kt = 0; kt < 8; kt++) {
        int kc = kt * 16 + kc0;
        float2 f0 = val0 ? *(const float2*)(xr0 + kc)     : fz;
        float2 f1 = val1 ? *(const float2*)(xr1 + kc)     : fz;
        float2 f2 = val0 ? *(const float2*)(xr0 + kc + 8) : fz;
        float2 f3 = val1 ? *(const float2*)(xr1 + kc + 8) : fz;
        unsigned ah[4], al[4];
        split2(f0, ah[0], al[0]);
        split2(f1, ah[1], al[1]);
        split2(f2, ah[2], al[2]);
        split2(f3, ah[3], al[3]);
#pragma unroll
        for (int nt = 0; nt < 16; nt++) {
            unsigned bAddr = sbase + OFF_BH +
                (unsigned)((nt * 8 + bRow) * 272 + (kt * 16 + bKoff) * 2);
            unsigned bh[2], bl[2];
            ldsm_x2(bh, bAddr);
            ldsm_x2(bl, bAddr + BT);
            mma16816(acc[nt], ah, bh);
            mma16816(acc[nt], ah, bl);
            mma16816(acc[nt], al, bh);
        }
    }

    // Epilogue: fp16 h1 store + head reductions (logits pre-scaled by log2e).
    {
        int c = lane & 3;
        float sv0[4] = {0, 0, 0, 0}, dv0[4] = {0, 0, 0, 0};
        float sv1[4] = {0, 0, 0, 0}, dv1[4] = {0, 0, 0, 0};
#pragma unroll
        for (int nt = 0; nt < 16; nt++) {
            int col = nt * 8 + 2 * c;
            float w0 = att_s[col], w1 = att_s[col + 1];
            float u0 = att_d[col], u1 = att_d[col + 1];
            int hd = nt >> 2;
            sv0[hd] += acc[nt][0] * w0 + acc[nt][1] * w1;
            dv0[hd] += acc[nt][0] * u0 + acc[nt][1] * u1;
            sv1[hd] += acc[nt][2] * w0 + acc[nt][3] * w1;
            dv1[hd] += acc[nt][2] * u0 + acc[nt][3] * u1;
            if (val0)
                g_h1h[(size_t)r0 * 64 + nt * 4 + c] =
                    __floats2half2_rn(acc[nt][0], acc[nt][1]);
            if (val1)
                g_h1h[(size_t)r1 * 64 + nt * 4 + c] =
                    __floats2half2_rn(acc[nt][2], acc[nt][3]);
        }
#pragma unroll
        for (int hd = 0; hd < 4; hd++) {
#pragma unroll
            for (int o = 1; o < 4; o <<= 1) {
                sv0[hd] += __shfl_xor_sync(0xffffffffu, sv0[hd], o);
                dv0[hd] += __shfl_xor_sync(0xffffffffu, dv0[hd], o);
                sv1[hd] += __shfl_xor_sync(0xffffffffu, sv1[hd], o);
                dv1[hd] += __shfl_xor_sync(0xffffffffu, dv1[hd], o);
            }
        }
        if (c == 0) {
#pragma unroll
            for (int hd = 0; hd < 4; hd++) {
                if (val0) {
                    g_as1[r0 * 4 + hd] = sv0[hd] * LOG2E;
                    g_ad1[r0 * 4 + hd] = dv0[hd] * LOG2E;
                }
                if (val1) {
                    g_as1[r1 * 4 + hd] = sv1[hd] * LOG2E;
                    g_ad1[r1 * 4 + hd] = dv1[hd] * LOG2E;
                }
            }
        }
    }
}

// ---------------- CSR scan: 4 items/thread, decoupled lookback --------------
__global__ void scan_kernel(int n, int tot) {
    __shared__ int warpsum[32];
    __shared__ int s_prev;
    int t = threadIdx.x, b = blockIdx.x;
    int lane = t & 31, wid = t >> 5;
    int base = (b * 1024 + t) * 4;
    int4 v = make_int4(0, 0, 0, 0);
    if (base + 3 < n) v = *(const int4*)&g_deg[base];
    else if (base < n) {
        v.x = g_deg[base];
        if (base + 1 < n) v.y = g_deg[base + 1];
        if (base + 2 < n) v.z = g_deg[base + 2];
    }
    int tsum = v.x + v.y + v.z + v.w;
    int x = tsum;
#pragma unroll
    for (int o = 1; o < 32; o <<= 1) {
        int y = __shfl_up_sync(0xffffffffu, x, o);
        if (lane >= o) x += y;
    }
    if (lane == 31) warpsum[wid] = x;
    __syncthreads();
    if (wid == 0) {
        int wv = warpsum[lane];
#pragma unroll
        for (int o = 1; o < 32; o <<= 1) {
            int y = __shfl_up_sync(0xffffffffu, wv, o);
            if (lane >= o) wv += y;
        }
        warpsum[lane] = wv;
    }
    __syncthreads();
    int incl = x + (wid ? warpsum[wid - 1] : 0);
    int agg = warpsum[31];

    if (b == 0) {
        if (t == 0) {
            *(volatile unsigned long long*)&g_scanpack[0] =
                (2ull << 32) | (unsigned)agg;
            s_prev = 0;
        }
    } else if (t < 32) {
        if (t == 0)
            *(volatile unsigned long long*)&g_scanpack[b] =
                (1ull << 32) | (unsigned)agg;
        __syncwarp();
        int sum = 0;
        int lb = b - 1;
        for (;;) {
            int j = lb - lane;
            unsigned long long w;
            unsigned f;
            for (;;) {
                w = (j >= 0) ? *(volatile unsigned long long*)&g_scanpack[j]
                             : (2ull << 32);
                f = (unsigned)(w >> 32);
                if (__all_sync(0xffffffffu, f != 0u)) break;
            }
            unsigned m2 = __ballot_sync(0xffffffffu, f == 2u);
            int fl = m2 ? (__ffs(m2) - 1) : 32;
            int take = (lane <= fl) ? (int)(unsigned)w : 0;
#pragma unroll
            for (int o = 16; o > 0; o >>= 1)
                take += __shfl_xor_sync(0xffffffffu, take, o);
            sum += take;
            if (m2) break;
            lb -= 32;
        }
        if (t == 0) {
            *(volatile unsigned long long*)&g_scanpack[b] =
                (2ull << 32) | (unsigned)(sum + agg);
            s_prev = sum;
        }
    }
    __syncthreads();
    if (base < n) {
        int r0 = s_prev + incl - tsum;
        int r1 = r0 + v.x, r2 = r1 + v.y, r3 = r2 + v.z;
        if (base + 3 < n) *(int4*)&g_rowptr[base] = make_int4(r0, r1, r2, r3);
        else {
            g_rowptr[base] = r0;
            if (base + 1 < n) g_rowptr[base + 1] = r1;
            if (base + 2 < n) g_rowptr[base + 2] = r2;
        }
    }
    if (b == 0 && t == 0) g_rowptr[n] = tot;
}

// -------- CSR scatter (rank-based, no atomics) + scratch self-clean ---------
__global__ void scatter_kernel(const void* __restrict__ ei, int e_cnt, int n) {
    int is64 = block_detect_is64(ei);
    int base = blockIdx.x * 1024 + threadIdx.x;
#pragma unroll
    for (int j = 0; j < 4; j++) {
        int i = base + j * 256;
        if (i < e_cnt) {
            int src, dst;
            edge_fetch(ei, e_cnt, i, is64, src, dst);
            g_esrc[g_rowptr[dst] + g_rank[i]] = src;
        }
    }
    // reset scratch for the next graph replay (deg/scanpack are dead here)
    int gid = blockIdx.x * 256 + threadIdx.x;
    if (gid < n) g_deg[gid] = 0;
    if (gid < 128) g_scanpack[gid] = 0ull;
}

// ------ layer-1 aggregation (warp per dst; HFMA2 accum, fp32 flush/8) -------
__global__ void agg1_kernel(const float* __restrict__ b1,
                            const float* __restrict__ W2, int n) {
    int v = (blockIdx.x * blockDim.x + threadIdx.x) >> 5;
    int lane = threadIdx.x & 31;
    if (v >= n) return;
    int hd = lane >> 3;
    int beg = g_rowptr[v];
    int end = g_rowptr[v + 1];
    float adv = g_ad1[v * 4 + hd];
    const uint2* H2 = (const uint2*)g_h1h;

    // self-loop contribution (fp32 path)
    float4 acc;
    float den;
    {
        float exs = exp_lrelu(g_as1[v * 4 + hd] + adv);
        uint2 pv = H2[v * 32 + lane];
        float2 q0 = __half22float2(*(__half2*)&pv.x);
        float2 q1 = __half22float2(*(__half2*)&pv.y);
        den = exs;
        acc = make_float4(q0.x * exs, q0.y * exs, q1.x * exs, q1.y * exs);
    }

    int e = beg;
    // main loop: 8 edges per block, half2 accumulation, fp32 flush
    for (; e + 7 < end; e += 8) {
        __half2 hacc0 = __float2half2_rn(0.f);
        __half2 hacc1 = __float2half2_rn(0.f);
        float dsum = 0.f;
#pragma unroll
        for (int j = 0; j < 8; j++) {
            int s = g_esrc[e + j];
            float ex = exp_lrelu(g_as1[s * 4 + hd] + adv);
            uint2 p = H2[s * 32 + lane];
            dsum += ex;
            __half2 exh = __float2half2_rn(ex);
            hacc0 = __hfma2(*(__half2*)&p.x, exh, hacc0);
            hacc1 = __hfma2(*(__half2*)&p.y, exh, hacc1);
        }
        den += dsum;
        float2 f0 = __half22float2(hacc0);
        float2 f1 = __half22float2(hacc1);
        acc.x += f0.x; acc.y += f0.y; acc.z += f1.x; acc.w += f1.y;
    }
    // remainder: fp32 path
    for (; e < end; e++) {
        int s = g_esrc[e];
        float ex = exp_lrelu(g_as1[s * 4 + hd] + adv);
        uint2 p = H2[s * 32 + lane];
        float2 q0 = __half22float2(*(__half2*)&p.x);
        float2 q1 = __half22float2(*(__half2*)&p.y);
        den += ex;
        acc.x += q0.x * ex; acc.y += q0.y * ex;
        acc.z += q1.x * ex; acc.w += q1.y * ex;
    }

    float inv = 1.f / (den + 1e-16f);
    float4 bb = ((const float4*)b1)[lane];
    float4 w  = ((const float4*)W2)[lane];
    float x0 = fmaxf(acc.x * inv + bb.x, 0.f);
    float x1 = fmaxf(acc.y * inv + bb.y, 0.f);
    float x2 = fmaxf(acc.z * inv + bb.z, 0.f);
    float x3 = fmaxf(acc.w * inv + bb.w, 0.f);
    float s = x0 * w.x + x1 * w.y + x2 * w.z + x3 * w.w;
#pragma unroll
    for (int o = 16; o > 0; o >>= 1) s += __shfl_xor_sync(0xffffffffu, s, o);
    if (lane == 0) g_h2[v] = s;
}

// -------- layer-2 aggregation (4 lanes per dst node; self-loop fused) -------
__global__ void agg2_kernel(const float* __restrict__ att_s2,
                            const float* __restrict__ att_d2,
                            const float* __restrict__ b2,
                            float* __restrict__ out, int n) {
    int tid = blockIdx.x * blockDim.x + threadIdx.x;
    int v = tid >> 2;
    int sub = tid & 3;
    bool valid = v < n;
    int vv = valid ? v : 0;
    float as2 = att_s2[0] * LOG2E;
    float hv = g_h2[vv];
    float adv = hv * (att_d2[0] * LOG2E);
    int beg = g_rowptr[vv];
    int end = valid ? g_rowptr[vv + 1] : beg;
    float den = 0.f, num = 0.f;
    if (sub == 0 && valid) {
        float exs = exp_lrelu(hv * as2 + adv);
        den = exs;
        num = hv * exs;
    }
    int e = beg + sub;
    for (; e + 4 < end; e += 8) {
        float h0 = g_h2[g_esrc[e]];
        float h1 = g_h2[g_esrc[e + 4]];
        float e0 = exp_lrelu(h0 * as2 + adv);
        float e1 = exp_lrelu(h1 * as2 + adv);
        den += e0 + e1;
        num += h0 * e0 + h1 * e1;
    }
    if (e < end) {
        float h0 = g_h2[g_esrc[e]];
        float e0 = exp_lrelu(h0 * as2 + adv);
        den += e0;
        num += h0 * e0;
    }
    den += __shfl_xor_sync(0xffffffffu, den, 1);
    num += __shfl_xor_sync(0xffffffffu, num, 1);
    den += __shfl_xor_sync(0xffffffffu, den, 2);
    num += __shfl_xor_sync(0xffffffffu, num, 2);
    if (valid && sub == 0) out[v] = num / (den + 1e-16f) + b2[0];
}

// ---------------- launch ------------------------------------------------------
extern "C" void kernel_launch(void* const* d_in, const int* in_sizes, int n_in,
                              void* d_out, int out_size) {
    const float* x        = (const float*)d_in[0];
    const void*  ei       = d_in[1];
    const float* W1       = (const float*)d_in[2];
    const float* att_src1 = (const float*)d_in[3];
    const float* att_dst1 = (const float*)d_in[4];
    const float* b1       = (const float*)d_in[5];
    const float* W2       = (const float*)d_in[6];
    const float* att_src2 = (const float*)d_in[7];
    const float* att_dst2 = (const float*)d_in[8];
    const float* b2       = (const float*)d_in[9];
    float* out = (float*)d_out;

    int n = in_sizes[0] / 128;
    int e = in_sizes[1] / 2;
    int nb = (n + 4095) / 4096;
    int gb = (n + 127) / 128;
    int hb = (e + 1023) / 1024;

    cudaFuncSetAttribute(fused_gemm_hist_kernel,
                         cudaFuncAttributeMaxDynamicSharedMemorySize, GEMM_SMEM);

    fused_gemm_hist_kernel<<<gb + hb, 256, GEMM_SMEM>>>(
        x, W1, att_src1, att_dst1, n, gb, ei, e);
    scan_kernel<<<nb, 1024>>>(n, e);
    scatter_kernel<<<hb, 256>>>(ei, e, n);
    agg1_kernel<<<(n + 7) / 8, 256>>>(b1, W2, n);
    agg2_kernel<<<(4 * n + 255) / 256, 256>>>(att_src2, att_dst2, b2, out, n);
}